// round 1
// baseline (speedup 1.0000x reference)
#include <cuda_runtime.h>

#define EPSV 1e-5f

// ---------------- device scratch (no cudaMalloc allowed) ----------------
__device__ float g_W1[272 * 459];   // folded conv1+A1+BN1 weights  [cw=c*17+w][dt*51 + u*3+ci]
__device__ float g_B1[272];
__device__ float g_W2[96 * 2448];   // folded conv2+parts+A2+BN2    [cw2=c*6+w][(f*17+jt)*9 + dt]
__device__ float g_B2[96];
__device__ float g_W3[16 * 480];    // BN3-folded conv3             [o][c*5+dk]
__device__ float g_B3[16];
__device__ float g_W4[64 * 48];     // BN4-folded conv4             [o][c*3+dk]
__device__ float g_B4[64];
__device__ float g_f1[16 * 272 * 2048];  // f1bn   [n][c*17+w][t]
__device__ float g_f2[16 * 96 * 2048];   // f2bn   [n][c*6+w][t]

// joint -> (body part, index within part)
__constant__ int c_part_of[17] = {1,2,3,1,1,4,4,5,5,2,2,3,3,0,0,0,0};
__constant__ int c_idx_of[17]  = {0,0,0,1,2,0,1,0,1,1,2,1,2,0,1,2,3};
__constant__ int c_len_of[6]   = {4,3,3,3,2,2};

// ---------------- weight folding kernels ----------------
__global__ void prep1(const float* __restrict__ A1, const float* __restrict__ w1,
                      const float* __restrict__ b1, const float* __restrict__ g1,
                      const float* __restrict__ be1, const float* __restrict__ m1,
                      const float* __restrict__ v1) {
    int cw = blockIdx.x;               // 0..271
    int c = cw / 17, w = cw % 17;
    float s = g1[cw] * rsqrtf(v1[cw] + EPSV);
    for (int e = threadIdx.x; e < 459; e += blockDim.x) {
        int dt = e / 51, r = e % 51, u = r / 3, ci = r % 3;
        float val = 0.f;
        for (int k = 0; k < 5; k++)
            for (int dv = 0; dv < 5; dv++) {
                int v = u - dv + 2;
                if (v >= 0 && v < 17)
                    val += A1[(k * 17 + v) * 17 + w] *
                           w1[(((k * 16 + c) * 3 + ci) * 9 + dt) * 5 + dv];
            }
        g_W1[cw * 459 + e] = val * s;
    }
    if (threadIdx.x == 0) {
        float bias = 0.f;
        for (int k = 0; k < 5; k++) {
            float sa = 0.f;
            for (int v = 0; v < 17; v++) sa += A1[(k * 17 + v) * 17 + w];
            bias += b1[k * 16 + c] * sa;
        }
        g_B1[cw] = (bias - m1[cw]) * s + be1[cw];
    }
}

__global__ void prep2(const float* __restrict__ A2, const float* __restrict__ w2,
                      const float* __restrict__ b2, const float* __restrict__ g2,
                      const float* __restrict__ be2, const float* __restrict__ m2,
                      const float* __restrict__ v2) {
    int cw = blockIdx.x;               // 0..95
    int c = cw / 6, w = cw % 6;
    float s = g2[cw] * rsqrtf(v2[cw] + EPSV);
    for (int e = threadIdx.x; e < 2448; e += blockDim.x) {
        int ch = e / 9, dt = e % 9;
        int f = ch / 17, jt = ch % 17;
        int p = c_part_of[jt], j = c_idx_of[jt], ln = c_len_of[p];
        int ci = f * ln + j;
        float val = 0.f;
        for (int k = 0; k < 5; k++)
            for (int v = 0; v < 6; v++) {
                int dp = p - v + 1;                 // conv over part axis, pad 1
                if (dp >= 0 && dp < 3)
                    val += A2[(k * 6 + v) * 6 + w] *
                           w2[(((k * 16 + c) * 64 + ci) * 9 + dt) * 3 + dp];
            }
        g_W2[cw * 2448 + e] = val * s;
    }
    if (threadIdx.x == 0) {
        float bias = 0.f;
        for (int k = 0; k < 5; k++) {
            float sa = 0.f;
            for (int v = 0; v < 6; v++) sa += A2[(k * 6 + v) * 6 + w];
            bias += b2[k * 16 + c] * sa;
        }
        g_B2[cw] = (bias - m2[cw]) * s + be2[cw];
    }
}

__global__ void prep34(const float* __restrict__ w3, const float* __restrict__ b3,
                       const float* __restrict__ g3, const float* __restrict__ be3,
                       const float* __restrict__ m3, const float* __restrict__ v3,
                       const float* __restrict__ w4, const float* __restrict__ b4,
                       const float* __restrict__ g4, const float* __restrict__ be4,
                       const float* __restrict__ m4, const float* __restrict__ v4) {
    for (int e = threadIdx.x; e < 7680; e += blockDim.x) {
        int o = e / 480;
        g_W3[e] = w3[e] * (g3[o] * rsqrtf(v3[o] + EPSV));
    }
    for (int e = threadIdx.x; e < 3072; e += blockDim.x) {
        int o = e / 48;
        g_W4[e] = w4[e] * (g4[o] * rsqrtf(v4[o] + EPSV));
    }
    if (threadIdx.x < 16) {
        int o = threadIdx.x;
        float s = g3[o] * rsqrtf(v3[o] + EPSV);
        g_B3[o] = (b3[o] - m3[o]) * s + be3[o];
    }
    if (threadIdx.x >= 32 && threadIdx.x < 96) {
        int o = threadIdx.x - 32;
        float s = g4[o] * rsqrtf(v4[o] + EPSV);
        g_B4[o] = (b4[o] - m4[o]) * s + be4[o];
    }
}

// ---------------- stage 1: f1bn = W1eff @ im2col(poses) ----------------
// grid (32, 16): t-tiles of 64 per batch.  C[272, 64] per CTA.
__global__ void __launch_bounds__(256) k1(const float* __restrict__ poses) {
    extern __shared__ float sm[];
    float* Ps = sm;              // [72][51]  poses tile (t halo +/-4)
    float* Ws = sm + 72 * 51;    // [272][51] one dt-slab of W1
    const int n = blockIdx.y;
    const int t0 = blockIdx.x * 64;
    const int tid = threadIdx.x;
    const int tx = tid & 15, ty = tid >> 4;

    for (int idx = tid; idx < 72 * 51; idx += 256) {
        int rr = idx / 51, r = idx - rr * 51;
        int t = t0 - 4 + rr;
        Ps[idx] = (t >= 0 && t < 2048) ? poses[(n * 2048 + t) * 51 + r] : 0.f;
    }

    float acc[17][4];
#pragma unroll
    for (int i = 0; i < 17; i++)
#pragma unroll
        for (int j = 0; j < 4; j++) acc[i][j] = 0.f;

    for (int dt = 0; dt < 9; dt++) {
        __syncthreads();
        for (int idx = tid; idx < 272 * 51; idx += 256) {
            int row = idx / 51, kk = idx - row * 51;
            Ws[idx] = g_W1[row * 459 + dt * 51 + kk];
        }
        __syncthreads();
        const float* pb = Ps + (tx + dt) * 51;
        for (int kk = 0; kk < 51; kk++) {
            float b[4];
#pragma unroll
            for (int j = 0; j < 4; j++) b[j] = pb[j * 16 * 51 + kk];
#pragma unroll
            for (int i = 0; i < 17; i++) {
                float a = Ws[(ty + 16 * i) * 51 + kk];
#pragma unroll
                for (int j = 0; j < 4; j++) acc[i][j] = fmaf(a, b[j], acc[i][j]);
            }
        }
    }
#pragma unroll
    for (int i = 0; i < 17; i++) {
        int cw = ty + 16 * i;
        float bb = g_B1[cw];
#pragma unroll
        for (int j = 0; j < 4; j++)
            g_f1[(n * 272 + cw) * 2048 + t0 + tx + 16 * j] = acc[i][j] + bb;
    }
}

// ---------------- stage 2: f2bn = W2eff @ im2col(f1bn) ----------------
// grid (16, 16): t-tiles of 128 per batch.  C[96, 128] per CTA. K streamed in 16-ch chunks.
__global__ void __launch_bounds__(256) k2() {
    extern __shared__ float sm[];
    float* F1s = sm;              // [16][136]  f1 chunk (t halo +/-4)
    float* W2s = sm + 16 * 136;   // [96][144]  W2 chunk (16 ch * 9 dt)
    const int n = blockIdx.y;
    const int t0 = blockIdx.x * 128;
    const int tid = threadIdx.x;
    const int tx = tid & 15, ty = tid >> 4;

    float acc[6][8];
#pragma unroll
    for (int i = 0; i < 6; i++)
#pragma unroll
        for (int j = 0; j < 8; j++) acc[i][j] = 0.f;

    for (int ch0 = 0; ch0 < 272; ch0 += 16) {
        __syncthreads();
        for (int idx = tid; idx < 16 * 136; idx += 256) {
            int c = idx / 136, rr = idx - c * 136;
            int t = t0 - 4 + rr;
            F1s[idx] = (t >= 0 && t < 2048) ? g_f1[(n * 272 + ch0 + c) * 2048 + t] : 0.f;
        }
        for (int idx = tid; idx < 96 * 144; idx += 256) {
            int row = idx / 144, kk = idx - row * 144;
            W2s[idx] = g_W2[row * 2448 + ch0 * 9 + kk];
        }
        __syncthreads();
        for (int c = 0; c < 16; c++) {
            const float* fb = F1s + c * 136 + tx;
#pragma unroll 3
            for (int dt = 0; dt < 9; dt++) {
                int kk = c * 9 + dt;
                float b[8];
#pragma unroll
                for (int j = 0; j < 8; j++) b[j] = fb[dt + 16 * j];
#pragma unroll
                for (int i = 0; i < 6; i++) {
                    float a = W2s[(ty + 16 * i) * 144 + kk];
#pragma unroll
                    for (int j = 0; j < 8; j++) acc[i][j] = fmaf(a, b[j], acc[i][j]);
                }
            }
        }
    }
#pragma unroll
    for (int i = 0; i < 6; i++) {
        int cw = ty + 16 * i;
        float bb = g_B2[cw];
#pragma unroll
        for (int j = 0; j < 8; j++)
            g_f2[(n * 96 + cw) * 2048 + t0 + tx + 16 * j] = acc[i][j] + bb;
    }
}

// ---------------- stages 3+4 fused: f3 (leaky) then f4 (leaky) -> out ----------------
// grid (16, 16): t-tiles of 128 per batch.
__global__ void __launch_bounds__(256) k34(float* __restrict__ out) {
    extern __shared__ float sm[];
    float* F2s = sm;                     // [96][134]  (t halo -3..+2 of tile+1)
    float* F3s = F2s + 96 * 134;         // [16][130]  (t halo +/-1)
    float* W3s = F3s + 16 * 130;         // 7680
    float* W4s = W3s + 7680;             // 3072
    const int n = blockIdx.y;
    const int t0 = blockIdx.x * 128;
    const int tid = threadIdx.x;

    for (int idx = tid; idx < 96 * 134; idx += 256) {
        int c = idx / 134, q = idx - c * 134;
        int t = t0 - 3 + q;
        F2s[idx] = (t >= 0 && t < 2048) ? g_f2[(n * 96 + c) * 2048 + t] : 0.f;
    }
    for (int idx = tid; idx < 7680; idx += 256) W3s[idx] = g_W3[idx];
    for (int idx = tid; idx < 3072; idx += 256) W4s[idx] = g_W4[idx];
    __syncthreads();

    // f3 for t in [t0-1, t0+128]  (130 positions; zero outside valid range = conv4 padding)
    for (int idx = tid; idx < 130 * 16; idx += 256) {
        int tp = idx % 130, o = idx / 130;
        int t3 = t0 - 1 + tp;
        float v = 0.f;
        if (t3 >= 0 && t3 < 2048) {
            float acc = g_B3[o];
            const float* wr = W3s + o * 480;
            for (int c = 0; c < 96; c++) {
                const float* f = F2s + c * 134 + tp;
#pragma unroll
                for (int dk = 0; dk < 5; dk++) acc = fmaf(wr[c * 5 + dk], f[dk], acc);
            }
            v = acc > 0.f ? acc : 0.01f * acc;
        }
        F3s[o * 130 + tp] = v;
    }
    __syncthreads();

    // f4 -> out[n][t][64]
    for (int idx = tid; idx < 128 * 64; idx += 256) {
        int o = idx & 63, tl = idx >> 6;
        float acc = g_B4[o];
        const float* wr = W4s + o * 48;
        const float* f = F3s + tl;
#pragma unroll
        for (int c = 0; c < 16; c++)
#pragma unroll
            for (int dk = 0; dk < 3; dk++)
                acc = fmaf(wr[c * 3 + dk], f[c * 130 + dk], acc);
        acc = acc > 0.f ? acc : 0.01f * acc;
        out[(n * 2048 + t0 + tl) * 64 + o] = acc;
    }
}

// ---------------- launch ----------------
extern "C" void kernel_launch(void* const* d_in, const int* in_sizes, int n_in,
                              void* d_out, int out_size) {
    (void)in_sizes; (void)n_in; (void)out_size;
    const float* poses = (const float*)d_in[0];
    const float* A1 = (const float*)d_in[1];
    const float* A2 = (const float*)d_in[2];
    const float* w1 = (const float*)d_in[3];
    const float* b1 = (const float*)d_in[4];
    const float* g1 = (const float*)d_in[5];
    const float* be1 = (const float*)d_in[6];
    const float* m1 = (const float*)d_in[7];
    const float* v1 = (const float*)d_in[8];
    const float* w2 = (const float*)d_in[9];
    const float* b2 = (const float*)d_in[10];
    const float* g2 = (const float*)d_in[11];
    const float* be2 = (const float*)d_in[12];
    const float* m2 = (const float*)d_in[13];
    const float* v2 = (const float*)d_in[14];
    const float* w3 = (const float*)d_in[15];
    const float* b3 = (const float*)d_in[16];
    const float* g3 = (const float*)d_in[17];
    const float* be3 = (const float*)d_in[18];
    const float* m3 = (const float*)d_in[19];
    const float* v3 = (const float*)d_in[20];
    const float* w4 = (const float*)d_in[21];
    const float* b4 = (const float*)d_in[22];
    const float* g4 = (const float*)d_in[23];
    const float* be4 = (const float*)d_in[24];
    const float* m4 = (const float*)d_in[25];
    const float* v4 = (const float*)d_in[26];
    float* out = (float*)d_out;

    size_t sm1 = (72 * 51 + 272 * 51) * sizeof(float);               // ~68.5 KB
    size_t sm2 = (16 * 136 + 96 * 144) * sizeof(float);              // 64 KB
    size_t sm34 = (96 * 134 + 16 * 130 + 7680 + 3072) * sizeof(float); // ~100 KB
    cudaFuncSetAttribute(k1, cudaFuncAttributeMaxDynamicSharedMemorySize, (int)sm1);
    cudaFuncSetAttribute(k2, cudaFuncAttributeMaxDynamicSharedMemorySize, (int)sm2);
    cudaFuncSetAttribute(k34, cudaFuncAttributeMaxDynamicSharedMemorySize, (int)sm34);

    prep1<<<272, 512>>>(A1, w1, b1, g1, be1, m1, v1);
    prep2<<<96, 256>>>(A2, w2, b2, g2, be2, m2, v2);
    prep34<<<1, 512>>>(w3, b3, g3, be3, m3, v3, w4, b4, g4, be4, m4, v4);
    k1<<<dim3(32, 16), 256, sm1>>>(poses);
    k2<<<dim3(16, 16), 256, sm2>>>();
    k34<<<dim3(16, 16), 256, sm34>>>(out);
}

// round 2
// speedup vs baseline: 1.0497x; 1.0497x over previous
#include <cuda_runtime.h>

#define EPSV 1e-5f

// ---------------- device scratch ----------------
__device__ float2 g_W1d[272 * 9 * 52];   // folded conv1+A1+BN1, dup'd {w,w}, [row][dt][kk(52,pad)]
__device__ float  g_B1[272];
__device__ float2 g_W2d[96 * 2448];      // folded conv2+parts+A2+BN2, dup'd, [row][kk=ch*9+dt]
__device__ float  g_B2[96];
__device__ float  g_W3[16 * 480];
__device__ float  g_B3[16];
__device__ float  g_W4[64 * 48];
__device__ float  g_B4[64];
__device__ float  g_f1[16 * 272 * 2048]; // f1bn [n][ch][t]
__device__ float  g_f2[16 * 96 * 2048];  // f2bn [n][ch][t]

__constant__ int c_part_of[17] = {1,2,3,1,1,4,4,5,5,2,2,3,3,0,0,0,0};
__constant__ int c_idx_of[17]  = {0,0,0,1,2,0,1,0,1,1,2,1,2,0,1,2,3};
__constant__ int c_len_of[6]   = {4,3,3,3,2,2};

// packed f32x2 FMA: d = a*b + d (lanewise)
#define FFMA2(d, a, b) asm("fma.rn.f32x2 %0, %1, %2, %0;" : "+l"(d) : "l"(a), "l"(b))

__device__ __forceinline__ void cpa16(void* dst, const void* src) {
    unsigned d = (unsigned)__cvta_generic_to_shared(dst);
    asm volatile("cp.async.cg.shared.global [%0], [%1], 16;" :: "r"(d), "l"(src));
}
__device__ __forceinline__ void cpa4z(void* dst, const void* src, bool valid) {
    unsigned d = (unsigned)__cvta_generic_to_shared(dst);
    int sz = valid ? 4 : 0;
    asm volatile("cp.async.ca.shared.global [%0], [%1], 4, %2;" :: "r"(d), "l"(src), "r"(sz));
}
#define CP_COMMIT() asm volatile("cp.async.commit_group;")
#define CP_WAIT1()  asm volatile("cp.async.wait_group 1;")
#define CP_WAIT0()  asm volatile("cp.async.wait_group 0;")

// ---------------- weight folding ----------------
__global__ void prep1(const float* __restrict__ A1, const float* __restrict__ w1,
                      const float* __restrict__ b1, const float* __restrict__ g1,
                      const float* __restrict__ be1, const float* __restrict__ m1,
                      const float* __restrict__ v1) {
    int cw = blockIdx.x;               // 0..271
    int c = cw / 17, w = cw % 17;
    float s = g1[cw] * rsqrtf(v1[cw] + EPSV);
    for (int e = threadIdx.x; e < 9 * 52; e += blockDim.x) {
        int dt = e / 52, kk = e % 52;
        float val = 0.f;
        if (kk < 51) {
            int u = kk / 3, ci = kk % 3;
            for (int k = 0; k < 5; k++)
                for (int dv = 0; dv < 5; dv++) {
                    int v = u - dv + 2;
                    if (v >= 0 && v < 17)
                        val += A1[(k * 17 + v) * 17 + w] *
                               w1[(((k * 16 + c) * 3 + ci) * 9 + dt) * 5 + dv];
                }
            val *= s;
        }
        g_W1d[(cw * 9 + dt) * 52 + kk] = make_float2(val, val);
    }
    if (threadIdx.x == 0) {
        float bias = 0.f;
        for (int k = 0; k < 5; k++) {
            float sa = 0.f;
            for (int v = 0; v < 17; v++) sa += A1[(k * 17 + v) * 17 + w];
            bias += b1[k * 16 + c] * sa;
        }
        g_B1[cw] = (bias - m1[cw]) * s + be1[cw];
    }
}

__global__ void prep2(const float* __restrict__ A2, const float* __restrict__ w2,
                      const float* __restrict__ b2, const float* __restrict__ g2,
                      const float* __restrict__ be2, const float* __restrict__ m2,
                      const float* __restrict__ v2) {
    int cw = blockIdx.x;               // 0..95
    int c = cw / 6, w = cw % 6;
    float s = g2[cw] * rsqrtf(v2[cw] + EPSV);
    for (int e = threadIdx.x; e < 2448; e += blockDim.x) {
        int ch = e / 9, dt = e % 9;
        int f = ch / 17, jt = ch % 17;
        int p = c_part_of[jt], j = c_idx_of[jt], ln = c_len_of[p];
        int ci = f * ln + j;
        float val = 0.f;
        for (int k = 0; k < 5; k++)
            for (int v = 0; v < 6; v++) {
                int dp = p - v + 1;
                if (dp >= 0 && dp < 3)
                    val += A2[(k * 6 + v) * 6 + w] *
                           w2[(((k * 16 + c) * 64 + ci) * 9 + dt) * 3 + dp];
            }
        val *= s;
        g_W2d[cw * 2448 + e] = make_float2(val, val);
    }
    if (threadIdx.x == 0) {
        float bias = 0.f;
        for (int k = 0; k < 5; k++) {
            float sa = 0.f;
            for (int v = 0; v < 6; v++) sa += A2[(k * 6 + v) * 6 + w];
            bias += b2[k * 16 + c] * sa;
        }
        g_B2[cw] = (bias - m2[cw]) * s + be2[cw];
    }
}

__global__ void prep34(const float* __restrict__ w3, const float* __restrict__ b3,
                       const float* __restrict__ g3, const float* __restrict__ be3,
                       const float* __restrict__ m3, const float* __restrict__ v3,
                       const float* __restrict__ w4, const float* __restrict__ b4,
                       const float* __restrict__ g4, const float* __restrict__ be4,
                       const float* __restrict__ m4, const float* __restrict__ v4) {
    for (int e = threadIdx.x; e < 7680; e += blockDim.x) {
        int o = e / 480;
        g_W3[e] = w3[e] * (g3[o] * rsqrtf(v3[o] + EPSV));
    }
    for (int e = threadIdx.x; e < 3072; e += blockDim.x) {
        int o = e / 48;
        g_W4[e] = w4[e] * (g4[o] * rsqrtf(v4[o] + EPSV));
    }
    if (threadIdx.x < 16) {
        int o = threadIdx.x;
        float s = g3[o] * rsqrtf(v3[o] + EPSV);
        g_B3[o] = (b3[o] - m3[o]) * s + be3[o];
    }
    if (threadIdx.x >= 32 && threadIdx.x < 96) {
        int o = threadIdx.x - 32;
        float s = g4[o] * rsqrtf(v4[o] + EPSV);
        g_B4[o] = (b4[o] - m4[o]) * s + be4[o];
    }
}

// ---------------- stage 1: f32x2 GEMM, tile 272 x 64, cp.async dbl-buffered W ----------------
// P4[s][kk] (stride 53 float4) = {x[t0-4+s+16j] for j=0..3}[kk]
__global__ void __launch_bounds__(256) k1(const float* __restrict__ poses) {
    extern __shared__ float sm[];
    float4* P4 = (float4*)sm;                      // [24][53] float4  = 20352 B
    float2* Wb = (float2*)(sm + 24 * 53 * 4);      // [2][272*26] float2 = 113152 B
    const int n = blockIdx.y, t0 = blockIdx.x * 64;
    const int tid = threadIdx.x, tx = tid & 15, ty = tid >> 4;

    for (int idx = tid; idx < 24 * 52 * 4; idx += 256) {
        int j = idx & 3, r = idx >> 2, kk = r % 52, s = r / 52;
        int t = t0 - 4 + s + 16 * j;
        float v = 0.f;
        if (kk < 51 && t >= 0 && t < 2048) v = __ldg(&poses[(n * 2048 + t) * 51 + kk]);
        ((float*)(P4 + s * 53 + kk))[j] = v;
    }

    auto prefetch = [&](int ch) {
        int dt = ch >> 1, half = ch & 1;
        const float2* src = g_W1d + dt * 52 + half * 26;
        float2* dst = Wb + (ch & 1) * (272 * 26);
        for (int idx = tid; idx < 272 * 13; idx += 256) {
            int row = idx / 13, q = idx % 13;
            cpa16(dst + row * 26 + 2 * q, src + row * (9 * 52) + 2 * q);
        }
        CP_COMMIT();
    };

    unsigned long long a01[17], a23[17];
#pragma unroll
    for (int i = 0; i < 17; i++) { a01[i] = 0ull; a23[i] = 0ull; }

    prefetch(0);
    for (int ch = 0; ch < 18; ch++) {
        if (ch + 1 < 18) { prefetch(ch + 1); CP_WAIT1(); } else { CP_WAIT0(); }
        __syncthreads();
        const int dt = ch >> 1;
        const float4* pb = P4 + (tx + dt) * 53 + (ch & 1) * 26;
        const float2* wl = Wb + (ch & 1) * (272 * 26) + ty * 26;
#pragma unroll
        for (int kp = 0; kp < 13; kp++) {
            ulonglong2 b0 = *(const ulonglong2*)(pb + 2 * kp);
            ulonglong2 b1 = *(const ulonglong2*)(pb + 2 * kp + 1);
#pragma unroll
            for (int i = 0; i < 17; i++) {
                ulonglong2 aa = *(const ulonglong2*)(wl + i * (16 * 26) + 2 * kp);
                FFMA2(a01[i], aa.x, b0.x); FFMA2(a23[i], aa.x, b0.y);
                FFMA2(a01[i], aa.y, b1.x); FFMA2(a23[i], aa.y, b1.y);
            }
        }
        __syncthreads();
    }

#pragma unroll
    for (int i = 0; i < 17; i++) {
        int row = ty + 16 * i;
        float bb = g_B1[row];
        union { unsigned long long u; float2 f; } u0, u1;
        u0.u = a01[i]; u1.u = a23[i];
        float* o = &g_f1[(n * 272 + row) * 2048 + t0 + tx];
        o[0]  = u0.f.x + bb; o[16] = u0.f.y + bb;
        o[32] = u1.f.x + bb; o[48] = u1.f.y + bb;
    }
}

// ---------------- stage 2: f32x2 GEMM, tile 96 x 128, C=4-channel chunks, dbl-buffered ----------------
__global__ void __launch_bounds__(256, 2) k2() {
    extern __shared__ float sm[];
    float4* F4 = (float4*)sm;                       // [2][24][9] float4 = 6912 B
    float2* Wb = (float2*)(sm + 2 * 24 * 9 * 4);    // [2][96*36] float2 = 55296 B
    const int n = blockIdx.y, t0 = blockIdx.x * 128;
    const int tid = threadIdx.x, tx = tid & 15, ty = tid >> 4;

    auto prefetch = [&](int ch) {
        int ch0 = ch * 4, buf = ch & 1;
        // weights: 96 rows x 36 kk (float2 dup'd)
        const float2* wsrc = g_W2d + ch0 * 9;
        float2* wdst = Wb + buf * (96 * 36);
        for (int idx = tid; idx < 96 * 18; idx += 256) {
            int row = idx / 18, q = idx % 18;
            cpa16(wdst + row * 36 + 2 * q, wsrc + row * 2448 + 2 * q);
        }
        // activations: F4[s][c][h] = f1[ch0+c][t0-4+s+16*(4h+jj)]
        float4* fdst = F4 + buf * (24 * 9);
        for (int idx = tid; idx < 24 * 4 * 8; idx += 256) {
            int j = idx & 7, r = idx >> 3, c = r & 3, s = r >> 2;
            int t = t0 - 4 + s + 16 * j;
            bool valid = (t >= 0 && t < 2048);
            const float* src = &g_f1[(n * 272 + ch0 + c) * 2048 + (valid ? t : 0)];
            cpa4z(((float*)(fdst + s * 9 + c * 2)) + j, src, valid);
        }
        CP_COMMIT();
    };

    unsigned long long a01[6], a23[6], a45[6], a67[6];
#pragma unroll
    for (int i = 0; i < 6; i++) { a01[i] = 0ull; a23[i] = 0ull; a45[i] = 0ull; a67[i] = 0ull; }

    prefetch(0);
    for (int ch = 0; ch < 68; ch++) {
        if (ch + 1 < 68) { prefetch(ch + 1); CP_WAIT1(); } else { CP_WAIT0(); }
        __syncthreads();
        const int buf = ch & 1;
        const float4* fb = F4 + buf * (24 * 9) + tx * 9;
        const float2* wl = Wb + buf * (96 * 36) + ty * 36;
#pragma unroll
        for (int kp = 0; kp < 18; kp++) {
            const int kl = 2 * kp, kl1 = 2 * kp + 1;
            const int c0 = kl / 9, d0 = kl % 9;
            const int c1 = kl1 / 9, d1 = kl1 % 9;
            const float4* p0 = fb + d0 * 9 + c0 * 2;
            const float4* p1 = fb + d1 * 9 + c1 * 2;
            ulonglong2 bA = *(const ulonglong2*)(p0);
            ulonglong2 bB = *(const ulonglong2*)(p0 + 1);
            ulonglong2 bC = *(const ulonglong2*)(p1);
            ulonglong2 bD = *(const ulonglong2*)(p1 + 1);
#pragma unroll
            for (int i = 0; i < 6; i++) {
                ulonglong2 aa = *(const ulonglong2*)(wl + i * (16 * 36) + kl);
                FFMA2(a01[i], aa.x, bA.x); FFMA2(a23[i], aa.x, bA.y);
                FFMA2(a45[i], aa.x, bB.x); FFMA2(a67[i], aa.x, bB.y);
                FFMA2(a01[i], aa.y, bC.x); FFMA2(a23[i], aa.y, bC.y);
                FFMA2(a45[i], aa.y, bD.x); FFMA2(a67[i], aa.y, bD.y);
            }
        }
        __syncthreads();
    }

#pragma unroll
    for (int i = 0; i < 6; i++) {
        int row = ty + 16 * i;
        float bb = g_B2[row];
        union { unsigned long long u; float2 f; } u0, u1, u2, u3;
        u0.u = a01[i]; u1.u = a23[i]; u2.u = a45[i]; u3.u = a67[i];
        float* o = &g_f2[(n * 96 + row) * 2048 + t0 + tx];
        o[0]   = u0.f.x + bb; o[16]  = u0.f.y + bb;
        o[32]  = u1.f.x + bb; o[48]  = u1.f.y + bb;
        o[64]  = u2.f.x + bb; o[80]  = u2.f.y + bb;
        o[96]  = u3.f.x + bb; o[112] = u3.f.y + bb;
    }
}

// ---------------- stages 3+4 fused ----------------
__global__ void __launch_bounds__(256) k34(float* __restrict__ out) {
    extern __shared__ float sm[];
    float* F2s = sm;                     // [96][134]
    float* F3s = F2s + 96 * 134;         // [16][130]
    float* W3s = F3s + 16 * 130;         // 7680
    float* W4s = W3s + 7680;             // 3072
    const int n = blockIdx.y;
    const int t0 = blockIdx.x * 128;
    const int tid = threadIdx.x;

    for (int idx = tid; idx < 96 * 134; idx += 256) {
        int c = idx / 134, q = idx - c * 134;
        int t = t0 - 3 + q;
        F2s[idx] = (t >= 0 && t < 2048) ? g_f2[(n * 96 + c) * 2048 + t] : 0.f;
    }
    for (int idx = tid; idx < 7680; idx += 256) W3s[idx] = g_W3[idx];
    for (int idx = tid; idx < 3072; idx += 256) W4s[idx] = g_W4[idx];
    __syncthreads();

    for (int idx = tid; idx < 130 * 16; idx += 256) {
        int tp = idx % 130, o = idx / 130;
        int t3 = t0 - 1 + tp;
        float v = 0.f;
        if (t3 >= 0 && t3 < 2048) {
            float acc = g_B3[o];
            const float* wr = W3s + o * 480;
            for (int c = 0; c < 96; c++) {
                const float* f = F2s + c * 134 + tp;
#pragma unroll
                for (int dk = 0; dk < 5; dk++) acc = fmaf(wr[c * 5 + dk], f[dk], acc);
            }
            v = acc > 0.f ? acc : 0.01f * acc;
        }
        F3s[o * 130 + tp] = v;
    }
    __syncthreads();

    for (int idx = tid; idx < 128 * 64; idx += 256) {
        int o = idx & 63, tl = idx >> 6;
        float acc = g_B4[o];
        const float* wr = W4s + o * 48;
        const float* f = F3s + tl;
#pragma unroll
        for (int c = 0; c < 16; c++)
#pragma unroll
            for (int dk = 0; dk < 3; dk++)
                acc = fmaf(wr[c * 3 + dk], f[c * 130 + dk], acc);
        acc = acc > 0.f ? acc : 0.01f * acc;
        out[(n * 2048 + t0 + tl) * 64 + o] = acc;
    }
}

// ---------------- launch ----------------
extern "C" void kernel_launch(void* const* d_in, const int* in_sizes, int n_in,
                              void* d_out, int out_size) {
    (void)in_sizes; (void)n_in; (void)out_size;
    const float* poses = (const float*)d_in[0];
    const float* A1 = (const float*)d_in[1];
    const float* A2 = (const float*)d_in[2];
    const float* w1 = (const float*)d_in[3];
    const float* b1 = (const float*)d_in[4];
    const float* g1 = (const float*)d_in[5];
    const float* be1 = (const float*)d_in[6];
    const float* m1 = (const float*)d_in[7];
    const float* v1 = (const float*)d_in[8];
    const float* w2 = (const float*)d_in[9];
    const float* b2 = (const float*)d_in[10];
    const float* g2 = (const float*)d_in[11];
    const float* be2 = (const float*)d_in[12];
    const float* m2 = (const float*)d_in[13];
    const float* v2 = (const float*)d_in[14];
    const float* w3 = (const float*)d_in[15];
    const float* b3 = (const float*)d_in[16];
    const float* g3 = (const float*)d_in[17];
    const float* be3 = (const float*)d_in[18];
    const float* m3 = (const float*)d_in[19];
    const float* v3 = (const float*)d_in[20];
    const float* w4 = (const float*)d_in[21];
    const float* b4 = (const float*)d_in[22];
    const float* g4 = (const float*)d_in[23];
    const float* be4 = (const float*)d_in[24];
    const float* m4 = (const float*)d_in[25];
    const float* v4 = (const float*)d_in[26];
    float* out = (float*)d_out;

    size_t sm1 = (24 * 53 * 4 + 2 * 272 * 26 * 2) * sizeof(float);     // 133504 B
    size_t sm2 = (2 * 24 * 9 * 4 + 2 * 96 * 36 * 2) * sizeof(float);   // 62208 B
    size_t sm34 = (96 * 134 + 16 * 130 + 7680 + 3072) * sizeof(float); // 102784 B
    cudaFuncSetAttribute(k1, cudaFuncAttributeMaxDynamicSharedMemorySize, (int)sm1);
    cudaFuncSetAttribute(k2, cudaFuncAttributeMaxDynamicSharedMemorySize, (int)sm2);
    cudaFuncSetAttribute(k34, cudaFuncAttributeMaxDynamicSharedMemorySize, (int)sm34);

    prep1<<<272, 512>>>(A1, w1, b1, g1, be1, m1, v1);
    prep2<<<96, 256>>>(A2, w2, b2, g2, be2, m2, v2);
    prep34<<<1, 512>>>(w3, b3, g3, be3, m3, v3, w4, b4, g4, be4, m4, v4);
    k1<<<dim3(32, 16), 256, sm1>>>(poses);
    k2<<<dim3(16, 16), 256, sm2>>>();
    k34<<<dim3(16, 16), 256, sm34>>>(out);
}

// round 3
// speedup vs baseline: 1.3590x; 1.2946x over previous
#include <cuda_runtime.h>
#include <cuda_bf16.h>

#define EPSV 1e-5f

// ---------------- device scratch ----------------
// tiled, split weights: [kc][mt][16 rows][24 cols(16 data + 8 pad)] bf16 bits
__device__ unsigned short g_W1h[29 * 17 * 16 * 24];
__device__ unsigned short g_W1l[29 * 17 * 16 * 24];
__device__ unsigned short g_W2h[153 * 6 * 16 * 24];
__device__ unsigned short g_W2l[153 * 6 * 16 * 24];
__device__ float g_B1[272];
__device__ float g_B2[96];
__device__ float g_W3[16 * 480];
__device__ float g_B3[16];
__device__ float g_W4[64 * 48];
__device__ float g_B4[64];
// transposed, split poses: [n][r=51][t=2048]
__device__ unsigned short g_Ph[16 * 51 * 2048];
__device__ unsigned short g_Pl[16 * 51 * 2048];
// f1 split bf16: [n][ch=272][t]
__device__ unsigned short g_f1h[16 * 272 * 2048];
__device__ unsigned short g_f1l[16 * 272 * 2048];
// f2 fp32: [n][ch=96][t]
__device__ float g_f2[16 * 96 * 2048];

__constant__ int c_part_of[17] = {1,2,3,1,1,4,4,5,5,2,2,3,3,0,0,0,0};
__constant__ int c_idx_of[17]  = {0,0,0,1,2,0,1,0,1,1,2,1,2,0,1,2,3};
__constant__ int c_len_of[6]   = {4,3,3,3,2,2};

// ---------------- helpers ----------------
__device__ __forceinline__ void split_bf16(float x, unsigned short& h, unsigned short& l) {
    __nv_bfloat16 bh = __float2bfloat16(x);
    float r = x - __bfloat162float(bh);
    __nv_bfloat16 bl = __float2bfloat16(r);
    h = __bfloat16_as_ushort(bh);
    l = __bfloat16_as_ushort(bl);
}

__device__ __forceinline__ void ldsm4(unsigned r[4], const void* p) {
    unsigned a = (unsigned)__cvta_generic_to_shared(p);
    asm volatile("ldmatrix.sync.aligned.m8n8.x4.shared.b16 {%0,%1,%2,%3},[%4];"
                 : "=r"(r[0]), "=r"(r[1]), "=r"(r[2]), "=r"(r[3]) : "r"(a));
}

__device__ __forceinline__ void mma_bf16(float* c, const unsigned* a, unsigned b0, unsigned b1) {
    asm volatile("mma.sync.aligned.m16n8k16.row.col.f32.bf16.bf16.f32 "
                 "{%0,%1,%2,%3},{%4,%5,%6,%7},{%8,%9},{%0,%1,%2,%3};"
                 : "+f"(c[0]), "+f"(c[1]), "+f"(c[2]), "+f"(c[3])
                 : "r"(a[0]), "r"(a[1]), "r"(a[2]), "r"(a[3]), "r"(b0), "r"(b1));
}

__device__ __forceinline__ void cpa16(void* dst, const void* src) {
    unsigned d = (unsigned)__cvta_generic_to_shared(dst);
    asm volatile("cp.async.cg.shared.global [%0], [%1], 16;" :: "r"(d), "l"(src));
}
#define CP_COMMIT() asm volatile("cp.async.commit_group;")
#define CP_WAIT0()  asm volatile("cp.async.wait_group 0;")

// ---------------- prep: transpose + split poses ----------------
__global__ void prepPoses(const float* __restrict__ poses) {
    int r = blockIdx.x, n = blockIdx.y;
    for (int t = threadIdx.x; t < 2048; t += blockDim.x) {
        float v = poses[((size_t)n * 2048 + t) * 51 + r];
        unsigned short h, l;
        split_bf16(v, h, l);
        size_t o = ((size_t)n * 51 + r) * 2048 + t;
        g_Ph[o] = h; g_Pl[o] = l;
    }
}

// ---------------- prep: fold + split + tile W1 ----------------
__global__ void prep1(const float* __restrict__ A1, const float* __restrict__ w1,
                      const float* __restrict__ b1, const float* __restrict__ g1,
                      const float* __restrict__ be1, const float* __restrict__ m1,
                      const float* __restrict__ v1) {
    int cw = blockIdx.x;               // 0..271
    int c = cw / 17, w = cw % 17;
    int mt = cw >> 4, row = cw & 15;
    float s = g1[cw] * rsqrtf(v1[cw] + EPSV);
    for (int kk = threadIdx.x; kk < 464; kk += blockDim.x) {
        float val = 0.f;
        if (kk < 459) {
            int dt = kk / 51, r = kk % 51, u = r / 3, ci = r % 3;
            for (int k = 0; k < 5; k++)
                for (int dv = 0; dv < 5; dv++) {
                    int v = u - dv + 2;
                    if (v >= 0 && v < 17)
                        val += A1[(k * 17 + v) * 17 + w] *
                               w1[(((k * 16 + c) * 3 + ci) * 9 + dt) * 5 + dv];
                }
            val *= s;
        }
        unsigned short h, l;
        split_bf16(val, h, l);
        int idx = (((kk >> 4) * 17 + mt) * 16 + row) * 24 + (kk & 15);
        g_W1h[idx] = h; g_W1l[idx] = l;
    }
    for (int e = threadIdx.x; e < 29 * 8; e += blockDim.x) {
        int kc = e >> 3, pc = e & 7;
        int idx = ((kc * 17 + mt) * 16 + row) * 24 + 16 + pc;
        g_W1h[idx] = 0; g_W1l[idx] = 0;
    }
    if (threadIdx.x == 0) {
        float bias = 0.f;
        for (int k = 0; k < 5; k++) {
            float sa = 0.f;
            for (int v = 0; v < 17; v++) sa += A1[(k * 17 + v) * 17 + w];
            bias += b1[k * 16 + c] * sa;
        }
        g_B1[cw] = (bias - m1[cw]) * s + be1[cw];
    }
}

// ---------------- prep: fold + split + tile W2 ----------------
__global__ void prep2(const float* __restrict__ A2, const float* __restrict__ w2,
                      const float* __restrict__ b2, const float* __restrict__ g2,
                      const float* __restrict__ be2, const float* __restrict__ m2,
                      const float* __restrict__ v2) {
    int cw = blockIdx.x;               // 0..95
    int c = cw / 6, w = cw % 6;
    int mt = cw >> 4, row = cw & 15;
    float s = g2[cw] * rsqrtf(v2[cw] + EPSV);
    for (int kk = threadIdx.x; kk < 2448; kk += blockDim.x) {
        int ch = kk / 9, dt = kk % 9;
        int f = ch / 17, jt = ch % 17;
        int p = c_part_of[jt], j = c_idx_of[jt], ln = c_len_of[p];
        int ci = f * ln + j;
        float val = 0.f;
        for (int k = 0; k < 5; k++)
            for (int v = 0; v < 6; v++) {
                int dp = p - v + 1;
                if (dp >= 0 && dp < 3)
                    val += A2[(k * 6 + v) * 6 + w] *
                           w2[(((k * 16 + c) * 64 + ci) * 9 + dt) * 3 + dp];
            }
        val *= s;
        unsigned short h, l;
        split_bf16(val, h, l);
        int idx = (((kk >> 4) * 6 + mt) * 16 + row) * 24 + (kk & 15);
        g_W2h[idx] = h; g_W2l[idx] = l;
    }
    for (int e = threadIdx.x; e < 153 * 8; e += blockDim.x) {
        int kc = e >> 3, pc = e & 7;
        int idx = ((kc * 6 + mt) * 16 + row) * 24 + 16 + pc;
        g_W2h[idx] = 0; g_W2l[idx] = 0;
    }
    if (threadIdx.x == 0) {
        float bias = 0.f;
        for (int k = 0; k < 5; k++) {
            float sa = 0.f;
            for (int v = 0; v < 6; v++) sa += A2[(k * 6 + v) * 6 + w];
            bias += b2[k * 16 + c] * sa;
        }
        g_B2[cw] = (bias - m2[cw]) * s + be2[cw];
    }
}

__global__ void prep34(const float* __restrict__ w3, const float* __restrict__ b3,
                       const float* __restrict__ g3, const float* __restrict__ be3,
                       const float* __restrict__ m3, const float* __restrict__ v3,
                       const float* __restrict__ w4, const float* __restrict__ b4,
                       const float* __restrict__ g4, const float* __restrict__ be4,
                       const float* __restrict__ m4, const float* __restrict__ v4) {
    for (int e = threadIdx.x; e < 7680; e += blockDim.x) {
        int o = e / 480;
        g_W3[e] = w3[e] * (g3[o] * rsqrtf(v3[o] + EPSV));
    }
    for (int e = threadIdx.x; e < 3072; e += blockDim.x) {
        int o = e / 48;
        g_W4[e] = w4[e] * (g4[o] * rsqrtf(v4[o] + EPSV));
    }
    if (threadIdx.x < 16) {
        int o = threadIdx.x;
        float s = g3[o] * rsqrtf(v3[o] + EPSV);
        g_B3[o] = (b3[o] - m3[o]) * s + be3[o];
    }
    if (threadIdx.x >= 32 && threadIdx.x < 96) {
        int o = threadIdx.x - 32;
        float s = g4[o] * rsqrtf(v4[o] + EPSV);
        g_B4[o] = (b4[o] - m4[o]) * s + be4[o];
    }
}

// ---------------- stage 1 tensor GEMM ----------------
// grid (16 tTiles, 16 n, 2 mHalf); block 256 (8 warps).
// C[ch-slice, 128 t] = W1 . X, bf16 3-term split, mma.m16n8k16.
// smem per buffer: Wh 6912 | Wl 6912 | Xh 6144 | Xl 6144 = 26112; x2 = 52224
#define K1_BUF 26112
__global__ void __launch_bounds__(256) k1() {
    extern __shared__ char sm[];
    const int n = blockIdx.y, t0 = blockIdx.x * 128;
    const int mt0 = blockIdx.z * 9, mcount = blockIdx.z ? 8 : 9;
    const int tid = threadIdx.x, lane = tid & 31, w = tid >> 5;
    const int tl = tid & 127, klbase = tid >> 7;

    float C[9][2][4];
#pragma unroll
    for (int i = 0; i < 9; i++)
#pragma unroll
        for (int j = 0; j < 2; j++)
#pragma unroll
            for (int q = 0; q < 4; q++) C[i][j][q] = 0.f;

    unsigned short hv[8], lv[8];

    auto prefW = [&](int kc, char* buf) {
        const char* srcH = (const char*)g_W1h + (size_t)(kc * 17 + mt0) * 768;
        const char* srcL = (const char*)g_W1l + (size_t)(kc * 17 + mt0) * 768;
        int cnt = mcount * 48;
        for (int i = tid; i < cnt; i += 256) {
            cpa16(buf + i * 16, srcH + i * 16);
            cpa16(buf + 6912 + i * 16, srcL + i * 16);
        }
    };
    auto loadX = [&](int kc) {
#pragma unroll
        for (int q = 0; q < 8; q++) {
            int kl = klbase + q * 2;
            int kk = kc * 16 + kl;
            unsigned short h = 0, l = 0;
            if (kk < 459) {
                int dt = kk / 51, r = kk - dt * 51;
                int t = t0 + tl + dt - 4;
                if (t >= 0 && t < 2048) {
                    size_t o = ((size_t)n * 51 + r) * 2048 + t;
                    h = g_Ph[o]; l = g_Pl[o];
                }
            }
            hv[q] = h; lv[q] = l;
        }
    };
    auto stsX = [&](char* buf) {
        unsigned short* Xh = (unsigned short*)(buf + 13824);
        unsigned short* Xl = (unsigned short*)(buf + 19968);
#pragma unroll
        for (int q = 0; q < 8; q++) {
            int kl = klbase + q * 2;
            Xh[tl * 24 + kl] = hv[q];
            Xl[tl * 24 + kl] = lv[q];
        }
    };

    prefW(0, sm); CP_COMMIT();
    loadX(0);

    const int lrow = (lane & 15) * 48 + (lane >> 4) * 16;
    const int ncol = lane >> 2, koff = (lane & 3) * 4;

    for (int kc = 0; kc < 29; kc++) {
        char* buf = sm + (kc & 1) * K1_BUF;
        stsX(buf);
        CP_WAIT0();
        __syncthreads();
        if (kc < 28) {
            prefW(kc + 1, sm + ((kc + 1) & 1) * K1_BUF);
            CP_COMMIT();
            loadX(kc + 1);
        }
        const char* Wh = buf;
        const char* Wl = buf + 6912;
        const char* Xh = buf + 13824;
        const char* Xl = buf + 19968;

        unsigned bh[2][2], bl[2][2];
#pragma unroll
        for (int nb = 0; nb < 2; nb++) {
            const char* p = Xh + (w * 16 + nb * 8 + ncol) * 48 + koff;
            bh[nb][0] = *(const unsigned*)p;
            bh[nb][1] = *(const unsigned*)(p + 16);
            const char* pl = Xl + (w * 16 + nb * 8 + ncol) * 48 + koff;
            bl[nb][0] = *(const unsigned*)pl;
            bl[nb][1] = *(const unsigned*)(pl + 16);
        }
        for (int mi = 0; mi < mcount; mi++) {
            unsigned Ah[4], Al[4];
            ldsm4(Ah, Wh + mi * 768 + lrow);
            ldsm4(Al, Wl + mi * 768 + lrow);
#pragma unroll
            for (int nb = 0; nb < 2; nb++) {
                mma_bf16(C[mi][nb], Ah, bh[nb][0], bh[nb][1]);
                mma_bf16(C[mi][nb], Ah, bl[nb][0], bl[nb][1]);
                mma_bf16(C[mi][nb], Al, bh[nb][0], bh[nb][1]);
            }
        }
        __syncthreads();
    }

    // epilogue: add bias, split to bf16 h/l, store
    for (int mi = 0; mi < mcount; mi++) {
#pragma unroll
        for (int nb = 0; nb < 2; nb++) {
            int ch0 = (mt0 + mi) * 16 + (lane >> 2);
            int tt = t0 + w * 16 + nb * 8 + (lane & 3) * 2;
            float b0 = g_B1[ch0], b1 = g_B1[ch0 + 8];
            unsigned short h0, l0, h1, l1;
            size_t o0 = ((size_t)n * 272 + ch0) * 2048 + tt;
            split_bf16(C[mi][nb][0] + b0, h0, l0);
            split_bf16(C[mi][nb][1] + b0, h1, l1);
            *(unsigned*)&g_f1h[o0] = (unsigned)h0 | ((unsigned)h1 << 16);
            *(unsigned*)&g_f1l[o0] = (unsigned)l0 | ((unsigned)l1 << 16);
            size_t o1 = ((size_t)n * 272 + ch0 + 8) * 2048 + tt;
            split_bf16(C[mi][nb][2] + b1, h0, l0);
            split_bf16(C[mi][nb][3] + b1, h1, l1);
            *(unsigned*)&g_f1h[o1] = (unsigned)h0 | ((unsigned)h1 << 16);
            *(unsigned*)&g_f1l[o1] = (unsigned)l0 | ((unsigned)l1 << 16);
        }
    }
}

// ---------------- stage 2 tensor GEMM ----------------
// grid (16 tTiles, 16 n); block 256. M=96 (6 mt), K=2448 (153 chunks).
// smem per buffer: Wh 4608 | Wl 4608 | Xh 6144 | Xl 6144 = 21504; x2 = 43008
#define K2_BUF 21504
__global__ void __launch_bounds__(256) k2() {
    extern __shared__ char sm[];
    const int n = blockIdx.y, t0 = blockIdx.x * 128;
    const int tid = threadIdx.x, lane = tid & 31, w = tid >> 5;
    const int tl = tid & 127, klbase = tid >> 7;

    float C[6][2][4];
#pragma unroll
    for (int i = 0; i < 6; i++)
#pragma unroll
        for (int j = 0; j < 2; j++)
#pragma unroll
            for (int q = 0; q < 4; q++) C[i][j][q] = 0.f;

    unsigned short hv[8], lv[8];

    auto prefW = [&](int kc, char* buf) {
        const char* srcH = (const char*)g_W2h + (size_t)kc * 4608;
        const char* srcL = (const char*)g_W2l + (size_t)kc * 4608;
        for (int i = tid; i < 288; i += 256) {
            cpa16(buf + i * 16, srcH + i * 16);
            cpa16(buf + 4608 + i * 16, srcL + i * 16);
        }
    };
    auto loadX = [&](int kc) {
#pragma unroll
        for (int q = 0; q < 8; q++) {
            int kl = klbase + q * 2;
            int kk = kc * 16 + kl;
            int ch = kk / 9, dt = kk - 9 * ch;
            int t = t0 + tl + dt - 4;
            unsigned short h = 0, l = 0;
            if (t >= 0 && t < 2048) {
                size_t o = ((size_t)n * 272 + ch) * 2048 + t;
                h = g_f1h[o]; l = g_f1l[o];
            }
            hv[q] = h; lv[q] = l;
        }
    };
    auto stsX = [&](char* buf) {
        unsigned short* Xh = (unsigned short*)(buf + 9216);
        unsigned short* Xl = (unsigned short*)(buf + 15360);
#pragma unroll
        for (int q = 0; q < 8; q++) {
            int kl = klbase + q * 2;
            Xh[tl * 24 + kl] = hv[q];
            Xl[tl * 24 + kl] = lv[q];
        }
    };

    prefW(0, sm); CP_COMMIT();
    loadX(0);

    const int lrow = (lane & 15) * 48 + (lane >> 4) * 16;
    const int ncol = lane >> 2, koff = (lane & 3) * 4;

    for (int kc = 0; kc < 153; kc++) {
        char* buf = sm + (kc & 1) * K2_BUF;
        stsX(buf);
        CP_WAIT0();
        __syncthreads();
        if (kc < 152) {
            prefW(kc + 1, sm + ((kc + 1) & 1) * K2_BUF);
            CP_COMMIT();
            loadX(kc + 1);
        }
        const char* Wh = buf;
        const char* Wl = buf + 4608;
        const char* Xh = buf + 9216;
        const char* Xl = buf + 15360;

        unsigned bh[2][2], bl[2][2];
#pragma unroll
        for (int nb = 0; nb < 2; nb++) {
            const char* p = Xh + (w * 16 + nb * 8 + ncol) * 48 + koff;
            bh[nb][0] = *(const unsigned*)p;
            bh[nb][1] = *(const unsigned*)(p + 16);
            const char* pl = Xl + (w * 16 + nb * 8 + ncol) * 48 + koff;
            bl[nb][0] = *(const unsigned*)pl;
            bl[nb][1] = *(const unsigned*)(pl + 16);
        }
#pragma unroll
        for (int mi = 0; mi < 6; mi++) {
            unsigned Ah[4], Al[4];
            ldsm4(Ah, Wh + mi * 768 + lrow);
            ldsm4(Al, Wl + mi * 768 + lrow);
#pragma unroll
            for (int nb = 0; nb < 2; nb++) {
                mma_bf16(C[mi][nb], Ah, bh[nb][0], bh[nb][1]);
                mma_bf16(C[mi][nb], Ah, bl[nb][0], bl[nb][1]);
                mma_bf16(C[mi][nb], Al, bh[nb][0], bh[nb][1]);
            }
        }
        __syncthreads();
    }

    // epilogue: bias + fp32 store for k34
#pragma unroll
    for (int mi = 0; mi < 6; mi++) {
#pragma unroll
        for (int nb = 0; nb < 2; nb++) {
            int ch0 = mi * 16 + (lane >> 2);
            int tt = t0 + w * 16 + nb * 8 + (lane & 3) * 2;
            float b0 = g_B2[ch0], b1 = g_B2[ch0 + 8];
            float2 v0 = make_float2(C[mi][nb][0] + b0, C[mi][nb][1] + b0);
            float2 v1 = make_float2(C[mi][nb][2] + b1, C[mi][nb][3] + b1);
            *(float2*)&g_f2[((size_t)n * 96 + ch0) * 2048 + tt] = v0;
            *(float2*)&g_f2[((size_t)n * 96 + ch0 + 8) * 2048 + tt] = v1;
        }
    }
}

// ---------------- stages 3+4 fused (fp32) ----------------
__global__ void __launch_bounds__(256) k34(float* __restrict__ out) {
    extern __shared__ float smf[];
    float* F2s = smf;                    // [96][134]
    float* F3s = F2s + 96 * 134;         // [16][130]
    float* W3s = F3s + 16 * 130;         // 7680
    float* W4s = W3s + 7680;             // 3072
    const int n = blockIdx.y;
    const int t0 = blockIdx.x * 128;
    const int tid = threadIdx.x;

    for (int idx = tid; idx < 96 * 134; idx += 256) {
        int c = idx / 134, q = idx - c * 134;
        int t = t0 - 3 + q;
        F2s[idx] = (t >= 0 && t < 2048) ? g_f2[((size_t)n * 96 + c) * 2048 + t] : 0.f;
    }
    for (int idx = tid; idx < 7680; idx += 256) W3s[idx] = g_W3[idx];
    for (int idx = tid; idx < 3072; idx += 256) W4s[idx] = g_W4[idx];
    __syncthreads();

    for (int idx = tid; idx < 130 * 16; idx += 256) {
        int tp = idx % 130, o = idx / 130;
        int t3 = t0 - 1 + tp;
        float v = 0.f;
        if (t3 >= 0 && t3 < 2048) {
            float acc = g_B3[o];
            const float* wr = W3s + o * 480;
            for (int c = 0; c < 96; c++) {
                const float* f = F2s + c * 134 + tp;
#pragma unroll
                for (int dk = 0; dk < 5; dk++) acc = fmaf(wr[c * 5 + dk], f[dk], acc);
            }
            v = acc > 0.f ? acc : 0.01f * acc;
        }
        F3s[o * 130 + tp] = v;
    }
    __syncthreads();

    for (int idx = tid; idx < 128 * 64; idx += 256) {
        int o = idx & 63, tl = idx >> 6;
        float acc = g_B4[o];
        const float* wr = W4s + o * 48;
        const float* f = F3s + tl;
#pragma unroll
        for (int c = 0; c < 16; c++)
#pragma unroll
            for (int dk = 0; dk < 3; dk++)
                acc = fmaf(wr[c * 3 + dk], f[c * 130 + dk], acc);
        acc = acc > 0.f ? acc : 0.01f * acc;
        out[((size_t)n * 2048 + t0 + tl) * 64 + o] = acc;
    }
}

// ---------------- launch ----------------
extern "C" void kernel_launch(void* const* d_in, const int* in_sizes, int n_in,
                              void* d_out, int out_size) {
    (void)in_sizes; (void)n_in; (void)out_size;
    const float* poses = (const float*)d_in[0];
    const float* A1 = (const float*)d_in[1];
    const float* A2 = (const float*)d_in[2];
    const float* w1 = (const float*)d_in[3];
    const float* b1 = (const float*)d_in[4];
    const float* g1 = (const float*)d_in[5];
    const float* be1 = (const float*)d_in[6];
    const float* m1 = (const float*)d_in[7];
    const float* v1 = (const float*)d_in[8];
    const float* w2 = (const float*)d_in[9];
    const float* b2 = (const float*)d_in[10];
    const float* g2 = (const float*)d_in[11];
    const float* be2 = (const float*)d_in[12];
    const float* m2 = (const float*)d_in[13];
    const float* v2 = (const float*)d_in[14];
    const float* w3 = (const float*)d_in[15];
    const float* b3 = (const float*)d_in[16];
    const float* g3 = (const float*)d_in[17];
    const float* be3 = (const float*)d_in[18];
    const float* m3 = (const float*)d_in[19];
    const float* v3 = (const float*)d_in[20];
    const float* w4 = (const float*)d_in[21];
    const float* b4 = (const float*)d_in[22];
    const float* g4 = (const float*)d_in[23];
    const float* be4 = (const float*)d_in[24];
    const float* m4 = (const float*)d_in[25];
    const float* v4 = (const float*)d_in[26];
    float* out = (float*)d_out;

    size_t sm1 = 2 * K1_BUF;                                            // 52224
    size_t sm2 = 2 * K2_BUF;                                            // 43008
    size_t sm34 = (96 * 134 + 16 * 130 + 7680 + 3072) * sizeof(float);  // 102784
    cudaFuncSetAttribute(k1, cudaFuncAttributeMaxDynamicSharedMemorySize, (int)sm1);
    cudaFuncSetAttribute(k2, cudaFuncAttributeMaxDynamicSharedMemorySize, (int)sm2);
    cudaFuncSetAttribute(k34, cudaFuncAttributeMaxDynamicSharedMemorySize, (int)sm34);

    prepPoses<<<dim3(51, 16), 256>>>(poses);
    prep1<<<272, 256>>>(A1, w1, b1, g1, be1, m1, v1);
    prep2<<<96, 256>>>(A2, w2, b2, g2, be2, m2, v2);
    prep34<<<1, 512>>>(w3, b3, g3, be3, m3, v3, w4, b4, g4, be4, m4, v4);
    k1<<<dim3(16, 16, 2), 256, sm1>>>();
    k2<<<dim3(16, 16), 256, sm2>>>();
    k34<<<dim3(16, 16), 256, sm34>>>(out);
}

// round 4
// speedup vs baseline: 1.7130x; 1.2605x over previous
#include <cuda_runtime.h>
#include <cuda_bf16.h>

#define EPSV 1e-5f

// ---------------- device scratch ----------------
// W1 tiles: [it=(dt*4+rc) 36][mt 17][16 rows][24 cols] bf16-bits (cols = r-local, pad/invalid = 0)
__device__ __align__(16) unsigned short g_W1h[36 * 17 * 16 * 24];
__device__ __align__(16) unsigned short g_W1l[36 * 17 * 16 * 24];
// W2 tiles: [it=(cc*9+dt) 153][mt 6][16 rows][24 cols]  (cols = ch-local)
__device__ __align__(16) unsigned short g_W2h[153 * 6 * 16 * 24];
__device__ __align__(16) unsigned short g_W2l[153 * 6 * 16 * 24];
__device__ float g_B1[272];
__device__ float g_B2[96];
__device__ float g_W3[16 * 480];
__device__ float g_B3[16];
__device__ float g_W4[64 * 48];
__device__ float g_B4[64];
// f1 split bf16: [n][ch=272][t]
__device__ __align__(16) unsigned short g_f1h[16 * 272 * 2048];
__device__ __align__(16) unsigned short g_f1l[16 * 272 * 2048];
// f2 fp32: [n][ch=96][t]
__device__ float g_f2[16 * 96 * 2048];

__constant__ int c_part_of[17] = {1,2,3,1,1,4,4,5,5,2,2,3,3,0,0,0,0};
__constant__ int c_idx_of[17]  = {0,0,0,1,2,0,1,0,1,1,2,1,2,0,1,2,3};
__constant__ int c_len_of[6]   = {4,3,3,3,2,2};

// ---------------- helpers ----------------
__device__ __forceinline__ void split_bf16(float x, unsigned short& h, unsigned short& l) {
    __nv_bfloat16 bh = __float2bfloat16(x);
    float r = x - __bfloat162float(bh);
    __nv_bfloat16 bl = __float2bfloat16(r);
    h = __bfloat16_as_ushort(bh);
    l = __bfloat16_as_ushort(bl);
}

__device__ __forceinline__ void ldsm4(unsigned r[4], const void* p) {
    unsigned a = (unsigned)__cvta_generic_to_shared(p);
    asm volatile("ldmatrix.sync.aligned.m8n8.x4.shared.b16 {%0,%1,%2,%3},[%4];"
                 : "=r"(r[0]), "=r"(r[1]), "=r"(r[2]), "=r"(r[3]) : "r"(a));
}

__device__ __forceinline__ void mma_bf16(float* c, const unsigned* a, unsigned b0, unsigned b1) {
    asm volatile("mma.sync.aligned.m16n8k16.row.col.f32.bf16.bf16.f32 "
                 "{%0,%1,%2,%3},{%4,%5,%6,%7},{%8,%9},{%0,%1,%2,%3};"
                 : "+f"(c[0]), "+f"(c[1]), "+f"(c[2]), "+f"(c[3])
                 : "r"(a[0]), "r"(a[1]), "r"(a[2]), "r"(a[3]), "r"(b0), "r"(b1));
}

__device__ __forceinline__ void cpa16(void* dst, const void* src) {
    unsigned d = (unsigned)__cvta_generic_to_shared(dst);
    asm volatile("cp.async.cg.shared.global [%0], [%1], 16;" :: "r"(d), "l"(src));
}
#define CP_COMMIT() asm volatile("cp.async.commit_group;")
#define CP_WAIT1()  asm volatile("cp.async.wait_group 1;")
#define CP_WAIT0()  asm volatile("cp.async.wait_group 0;")

// ---------------- prep: fold + split + tile W1 ----------------
__global__ void prep1(const float* __restrict__ A1, const float* __restrict__ w1,
                      const float* __restrict__ b1, const float* __restrict__ g1,
                      const float* __restrict__ be1, const float* __restrict__ m1,
                      const float* __restrict__ v1) {
    int cw = blockIdx.x;               // 0..271
    int c = cw / 17, w = cw % 17;
    int mt = cw >> 4, row = cw & 15;
    float s = g1[cw] * rsqrtf(v1[cw] + EPSV);
    for (int e = threadIdx.x; e < 36 * 24; e += blockDim.x) {
        int it = e / 24, col = e % 24;      // it = dt*4+rc
        int dt = it >> 2, rc = it & 3;
        int r = rc * 16 + col;
        float val = 0.f;
        if (col < 16 && r < 51) {
            int u = r / 3, ci = r % 3;
            for (int k = 0; k < 5; k++)
                for (int dv = 0; dv < 5; dv++) {
                    int v = u - dv + 2;
                    if (v >= 0 && v < 17)
                        val += A1[(k * 17 + v) * 17 + w] *
                               w1[(((k * 16 + c) * 3 + ci) * 9 + dt) * 5 + dv];
                }
            val *= s;
        }
        unsigned short h, l;
        split_bf16(val, h, l);
        int idx = ((it * 17 + mt) * 16 + row) * 24 + col;
        g_W1h[idx] = h; g_W1l[idx] = l;
    }
    if (threadIdx.x == 0) {
        float bias = 0.f;
        for (int k = 0; k < 5; k++) {
            float sa = 0.f;
            for (int v = 0; v < 17; v++) sa += A1[(k * 17 + v) * 17 + w];
            bias += b1[k * 16 + c] * sa;
        }
        g_B1[cw] = (bias - m1[cw]) * s + be1[cw];
    }
}

// ---------------- prep: fold + split + tile W2 ----------------
__global__ void prep2(const float* __restrict__ A2, const float* __restrict__ w2,
                      const float* __restrict__ b2, const float* __restrict__ g2,
                      const float* __restrict__ be2, const float* __restrict__ m2,
                      const float* __restrict__ v2) {
    int cw = blockIdx.x;               // 0..95
    int c = cw / 6, w = cw % 6;
    int mt = cw >> 4, row = cw & 15;
    float s = g2[cw] * rsqrtf(v2[cw] + EPSV);
    for (int e = threadIdx.x; e < 153 * 24; e += blockDim.x) {
        int it = e / 24, col = e % 24;      // it = cc*9+dt
        int cc = it / 9, dt = it % 9;
        int ch = cc * 16 + col;
        float val = 0.f;
        if (col < 16) {
            int f = ch / 17, jt = ch % 17;
            int p = c_part_of[jt], j = c_idx_of[jt], ln = c_len_of[p];
            int ci = f * ln + j;
            for (int k = 0; k < 5; k++)
                for (int v = 0; v < 6; v++) {
                    int dp = p - v + 1;
                    if (dp >= 0 && dp < 3)
                        val += A2[(k * 6 + v) * 6 + w] *
                               w2[(((k * 16 + c) * 64 + ci) * 9 + dt) * 3 + dp];
                }
            val *= s;
        }
        unsigned short h, l;
        split_bf16(val, h, l);
        int idx = ((it * 6 + mt) * 16 + row) * 24 + col;
        g_W2h[idx] = h; g_W2l[idx] = l;
    }
    if (threadIdx.x == 0) {
        float bias = 0.f;
        for (int k = 0; k < 5; k++) {
            float sa = 0.f;
            for (int v = 0; v < 6; v++) sa += A2[(k * 6 + v) * 6 + w];
            bias += b2[k * 16 + c] * sa;
        }
        g_B2[cw] = (bias - m2[cw]) * s + be2[cw];
    }
}

__global__ void prep34(const float* __restrict__ w3, const float* __restrict__ b3,
                       const float* __restrict__ g3, const float* __restrict__ be3,
                       const float* __restrict__ m3, const float* __restrict__ v3,
                       const float* __restrict__ w4, const float* __restrict__ b4,
                       const float* __restrict__ g4, const float* __restrict__ be4,
                       const float* __restrict__ m4, const float* __restrict__ v4) {
    for (int e = threadIdx.x; e < 7680; e += blockDim.x) {
        int o = e / 480;
        g_W3[e] = w3[e] * (g3[o] * rsqrtf(v3[o] + EPSV));
    }
    for (int e = threadIdx.x; e < 3072; e += blockDim.x) {
        int o = e / 48;
        g_W4[e] = w4[e] * (g4[o] * rsqrtf(v4[o] + EPSV));
    }
    if (threadIdx.x < 16) {
        int o = threadIdx.x;
        float s = g3[o] * rsqrtf(v3[o] + EPSV);
        g_B3[o] = (b3[o] - m3[o]) * s + be3[o];
    }
    if (threadIdx.x >= 32 && threadIdx.x < 96) {
        int o = threadIdx.x - 32;
        float s = g4[o] * rsqrtf(v4[o] + EPSV);
        g_B4[o] = (b4[o] - m4[o]) * s + be4[o];
    }
}

// ---------------- stage 1 tensor GEMM (dt-factored) ----------------
// grid (8 tTiles [N=256], 16 n, 4 mQuarters). 256 thr (8 warps, nb=4).
// X tile [264 rows tt][72 cols] ushort (cols 0..63 = r padded; stride 144B).
// smem: Wbuf0 7680 | Wbuf1 7680 | Xh 38016 | Xl 38016 = 91392 B
#define K1_XOFF 15360
#define K1_XSZ  38016
__global__ void __launch_bounds__(256) k1(const float* __restrict__ poses) {
    extern __shared__ char sm[];
    const int n = blockIdx.y, t0 = blockIdx.x * 256;
    const int z = blockIdx.z;
    const int mt0 = (z == 0) ? 0 : 1 + z * 4;          // 0,5,9,13
    const int mcount = (z == 0) ? 5 : 4;
    const int tid = threadIdx.x, lane = tid & 31, w = tid >> 5;

    unsigned short* Xh = (unsigned short*)(sm + K1_XOFF);
    unsigned short* Xl = (unsigned short*)(sm + K1_XOFF + K1_XSZ);

    auto prefW = [&](int it, char* buf) {
        const char* srcH = (const char*)(g_W1h + (size_t)(it * 17 + mt0) * 384);
        const char* srcL = (const char*)(g_W1l + (size_t)(it * 17 + mt0) * 384);
        int cnt = mcount * 48;
        for (int i = tid; i < cnt; i += 256) {
            cpa16(buf + i * 16, srcH + i * 16);
            cpa16(buf + 3840 + i * 16, srcL + i * 16);
        }
    };

    prefW(0, sm); CP_COMMIT();

    // load X tile: rows tt=0..263 (t = t0-4+tt), cols e=0..63 (r, zero-pad >=51)
    for (int idx = tid; idx < 264 * 64; idx += 256) {
        int tt = idx >> 6, e = idx & 63;
        int t = t0 - 4 + tt;
        float v = 0.f;
        if (e < 51 && t >= 0 && t < 2048) v = __ldg(&poses[((size_t)n * 2048 + t) * 51 + e]);
        unsigned short h, l;
        split_bf16(v, h, l);
        Xh[tt * 72 + e] = h; Xl[tt * 72 + e] = l;
    }

    float C[5][4][4];
#pragma unroll
    for (int i = 0; i < 5; i++)
#pragma unroll
        for (int j = 0; j < 4; j++)
#pragma unroll
            for (int q = 0; q < 4; q++) C[i][j][q] = 0.f;

    const int lrow = (lane & 15) * 48 + (lane >> 4) * 16;

    for (int it = 0; it < 36; it++) {
        char* buf = sm + (it & 1) * 7680;
        if (it + 1 < 36) { prefW(it + 1, sm + ((it + 1) & 1) * 7680); CP_COMMIT(); CP_WAIT1(); }
        else CP_WAIT0();
        __syncthreads();

        const int dt = it >> 2, rc = it & 3;
        const int colb = (rc * 16 + (lane & 3) * 2) * 2;   // byte offset in X row
        unsigned bh[4][2], bl[4][2];
#pragma unroll
        for (int nb = 0; nb < 4; nb++) {
            int tt = w * 32 + nb * 8 + (lane >> 2) + dt;
            const char* ph = (const char*)Xh + tt * 144 + colb;
            const char* pl = (const char*)Xl + tt * 144 + colb;
            bh[nb][0] = *(const unsigned*)ph; bh[nb][1] = *(const unsigned*)(ph + 16);
            bl[nb][0] = *(const unsigned*)pl; bl[nb][1] = *(const unsigned*)(pl + 16);
        }
        for (int mi = 0; mi < mcount; mi++) {
            unsigned Ah[4], Al[4];
            ldsm4(Ah, buf + mi * 768 + lrow);
            ldsm4(Al, buf + 3840 + mi * 768 + lrow);
#pragma unroll
            for (int nb = 0; nb < 4; nb++) {
                mma_bf16(C[mi][nb], Ah, bh[nb][0], bh[nb][1]);
                mma_bf16(C[mi][nb], Ah, bl[nb][0], bl[nb][1]);
                mma_bf16(C[mi][nb], Al, bh[nb][0], bh[nb][1]);
            }
        }
        __syncthreads();
    }

    // epilogue: bias + split store
    for (int mi = 0; mi < mcount; mi++) {
#pragma unroll
        for (int nb = 0; nb < 4; nb++) {
            int ch0 = (mt0 + mi) * 16 + (lane >> 2);
            int tt = t0 + w * 32 + nb * 8 + (lane & 3) * 2;
            float b0 = g_B1[ch0], b1 = g_B1[ch0 + 8];
            unsigned short h0, l0, h1, l1;
            size_t o0 = ((size_t)n * 272 + ch0) * 2048 + tt;
            split_bf16(C[mi][nb][0] + b0, h0, l0);
            split_bf16(C[mi][nb][1] + b0, h1, l1);
            *(unsigned*)&g_f1h[o0] = (unsigned)h0 | ((unsigned)h1 << 16);
            *(unsigned*)&g_f1l[o0] = (unsigned)l0 | ((unsigned)l1 << 16);
            size_t o1 = ((size_t)n * 272 + ch0 + 8) * 2048 + tt;
            split_bf16(C[mi][nb][2] + b1, h0, l0);
            split_bf16(C[mi][nb][3] + b1, h1, l1);
            *(unsigned*)&g_f1h[o1] = (unsigned)h0 | ((unsigned)h1 << 16);
            *(unsigned*)&g_f1l[o1] = (unsigned)l0 | ((unsigned)l1 << 16);
        }
    }
}

// ---------------- stage 2 tensor GEMM (dt-factored) ----------------
// grid (8 tTiles [N=256], 16 n). 256 thr. M=96. K = 17 ch-chunks x 9 dt.
// X tile [264 rows][24 cols] ushort (cols 0..15 = ch-local; stride 48B), reloaded per cc.
// smem: Wbuf0 9216 | Wbuf1 9216 | Xh 12672 | Xl 12672 = 43776 B
#define K2_XOFF 18432
#define K2_XSZ  12672
__global__ void __launch_bounds__(256) k2() {
    extern __shared__ char sm[];
    const int n = blockIdx.y, t0 = blockIdx.x * 256;
    const int tid = threadIdx.x, lane = tid & 31, w = tid >> 5;

    unsigned short* Xh = (unsigned short*)(sm + K2_XOFF);
    unsigned short* Xl = (unsigned short*)(sm + K2_XOFF + K2_XSZ);

    auto prefW = [&](int it, char* buf) {
        const char* srcH = (const char*)(g_W2h + (size_t)it * 2304);   // 6*384
        const char* srcL = (const char*)(g_W2l + (size_t)it * 2304);
        for (int i = tid; i < 288; i += 256) {
            cpa16(buf + i * 16, srcH + i * 16);
            cpa16(buf + 4608 + i * 16, srcL + i * 16);
        }
    };
    auto loadX = [&](int cc) {
        for (int ch = 0; ch < 16; ch++) {
            const unsigned short* sh = &g_f1h[((size_t)n * 272 + cc * 16 + ch) * 2048];
            const unsigned short* sl = &g_f1l[((size_t)n * 272 + cc * 16 + ch) * 2048];
            for (int tt = tid; tt < 264; tt += 256) {
                int t = t0 - 4 + tt;
                unsigned short h = 0, l = 0;
                if (t >= 0 && t < 2048) { h = sh[t]; l = sl[t]; }
                Xh[tt * 24 + ch] = h; Xl[tt * 24 + ch] = l;
            }
        }
    };

    float C[6][4][4];
#pragma unroll
    for (int i = 0; i < 6; i++)
#pragma unroll
        for (int j = 0; j < 4; j++)
#pragma unroll
            for (int q = 0; q < 4; q++) C[i][j][q] = 0.f;

    const int lrow = (lane & 15) * 48 + (lane >> 4) * 16;
    const int colb = ((lane & 3) * 2) * 2;

    prefW(0, sm); CP_COMMIT();

    for (int it = 0; it < 153; it++) {
        const int cc = it / 9, dt = it - cc * 9;
        if (dt == 0) loadX(cc);
        char* buf = sm + (it & 1) * 9216;
        if (it + 1 < 153) { prefW(it + 1, sm + ((it + 1) & 1) * 9216); CP_COMMIT(); CP_WAIT1(); }
        else CP_WAIT0();
        __syncthreads();

        unsigned bh[4][2], bl[4][2];
#pragma unroll
        for (int nb = 0; nb < 4; nb++) {
            int tt = w * 32 + nb * 8 + (lane >> 2) + dt;
            const char* ph = (const char*)Xh + tt * 48 + colb;
            const char* pl = (const char*)Xl + tt * 48 + colb;
            bh[nb][0] = *(const unsigned*)ph; bh[nb][1] = *(const unsigned*)(ph + 16);
            bl[nb][0] = *(const unsigned*)pl; bl[nb][1] = *(const unsigned*)(pl + 16);
        }
#pragma unroll
        for (int mi = 0; mi < 6; mi++) {
            unsigned Ah[4], Al[4];
            ldsm4(Ah, buf + mi * 768 + lrow);
            ldsm4(Al, buf + 4608 + mi * 768 + lrow);
#pragma unroll
            for (int nb = 0; nb < 4; nb++) {
                mma_bf16(C[mi][nb], Ah, bh[nb][0], bh[nb][1]);
                mma_bf16(C[mi][nb], Ah, bl[nb][0], bl[nb][1]);
                mma_bf16(C[mi][nb], Al, bh[nb][0], bh[nb][1]);
            }
        }
        __syncthreads();
    }

    // epilogue: bias + fp32 store [ch][t]
#pragma unroll
    for (int mi = 0; mi < 6; mi++) {
#pragma unroll
        for (int nb = 0; nb < 4; nb++) {
            int ch0 = mi * 16 + (lane >> 2);
            int tt = t0 + w * 32 + nb * 8 + (lane & 3) * 2;
            float b0 = g_B2[ch0], b1 = g_B2[ch0 + 8];
            float2 v0 = make_float2(C[mi][nb][0] + b0, C[mi][nb][1] + b0);
            float2 v1 = make_float2(C[mi][nb][2] + b1, C[mi][nb][3] + b1);
            *(float2*)&g_f2[((size_t)n * 96 + ch0) * 2048 + tt] = v0;
            *(float2*)&g_f2[((size_t)n * 96 + ch0 + 8) * 2048 + tt] = v1;
        }
    }
}

// ---------------- stages 3+4 fused (fp32) ----------------
__global__ void __launch_bounds__(256) k34(float* __restrict__ out) {
    extern __shared__ float smf[];
    float* F2s = smf;                    // [96][134]
    float* F3s = F2s + 96 * 134;         // [16][130]
    float* W3s = F3s + 16 * 130;         // 7680
    float* W4s = W3s + 7680;             // 3072
    const int n = blockIdx.y;
    const int t0 = blockIdx.x * 128;
    const int tid = threadIdx.x;

    for (int idx = tid; idx < 96 * 134; idx += 256) {
        int c = idx / 134, q = idx - c * 134;
        int t = t0 - 3 + q;
        F2s[idx] = (t >= 0 && t < 2048) ? g_f2[((size_t)n * 96 + c) * 2048 + t] : 0.f;
    }
    for (int idx = tid; idx < 7680; idx += 256) W3s[idx] = g_W3[idx];
    for (int idx = tid; idx < 3072; idx += 256) W4s[idx] = g_W4[idx];
    __syncthreads();

    for (int idx = tid; idx < 130 * 16; idx += 256) {
        int tp = idx % 130, o = idx / 130;
        int t3 = t0 - 1 + tp;
        float v = 0.f;
        if (t3 >= 0 && t3 < 2048) {
            float acc = g_B3[o];
            const float* wr = W3s + o * 480;
            for (int c = 0; c < 96; c++) {
                const float* f = F2s + c * 134 + tp;
#pragma unroll
                for (int dk = 0; dk < 5; dk++) acc = fmaf(wr[c * 5 + dk], f[dk], acc);
            }
            v = acc > 0.f ? acc : 0.01f * acc;
        }
        F3s[o * 130 + tp] = v;
    }
    __syncthreads();

    for (int idx = tid; idx < 128 * 64; idx += 256) {
        int o = idx & 63, tl = idx >> 6;
        float acc = g_B4[o];
        const float* wr = W4s + o * 48;
        const float* f = F3s + tl;
#pragma unroll
        for (int c = 0; c < 16; c++)
#pragma unroll
            for (int dk = 0; dk < 3; dk++)
                acc = fmaf(wr[c * 3 + dk], f[c * 130 + dk], acc);
        acc = acc > 0.f ? acc : 0.01f * acc;
        out[((size_t)n * 2048 + t0 + tl) * 64 + o] = acc;
    }
}

// ---------------- launch ----------------
extern "C" void kernel_launch(void* const* d_in, const int* in_sizes, int n_in,
                              void* d_out, int out_size) {
    (void)in_sizes; (void)n_in; (void)out_size;
    const float* poses = (const float*)d_in[0];
    const float* A1 = (const float*)d_in[1];
    const float* A2 = (const float*)d_in[2];
    const float* w1 = (const float*)d_in[3];
    const float* b1 = (const float*)d_in[4];
    const float* g1 = (const float*)d_in[5];
    const float* be1 = (const float*)d_in[6];
    const float* m1 = (const float*)d_in[7];
    const float* v1 = (const float*)d_in[8];
    const float* w2 = (const float*)d_in[9];
    const float* b2 = (const float*)d_in[10];
    const float* g2 = (const float*)d_in[11];
    const float* be2 = (const float*)d_in[12];
    const float* m2 = (const float*)d_in[13];
    const float* v2 = (const float*)d_in[14];
    const float* w3 = (const float*)d_in[15];
    const float* b3 = (const float*)d_in[16];
    const float* g3 = (const float*)d_in[17];
    const float* be3 = (const float*)d_in[18];
    const float* m3 = (const float*)d_in[19];
    const float* v3 = (const float*)d_in[20];
    const float* w4 = (const float*)d_in[21];
    const float* b4 = (const float*)d_in[22];
    const float* g4 = (const float*)d_in[23];
    const float* be4 = (const float*)d_in[24];
    const float* m4 = (const float*)d_in[25];
    const float* v4 = (const float*)d_in[26];
    float* out = (float*)d_out;

    size_t sm1 = 91392;
    size_t sm2 = 43776;
    size_t sm34 = (96 * 134 + 16 * 130 + 7680 + 3072) * sizeof(float);  // 102784
    cudaFuncSetAttribute(k1, cudaFuncAttributeMaxDynamicSharedMemorySize, (int)sm1);
    cudaFuncSetAttribute(k2, cudaFuncAttributeMaxDynamicSharedMemorySize, (int)sm2);
    cudaFuncSetAttribute(k34, cudaFuncAttributeMaxDynamicSharedMemorySize, (int)sm34);

    prep1<<<272, 256>>>(A1, w1, b1, g1, be1, m1, v1);
    prep2<<<96, 256>>>(A2, w2, b2, g2, be2, m2, v2);
    prep34<<<1, 512>>>(w3, b3, g3, be3, m3, v3, w4, b4, g4, be4, m4, v4);
    k1<<<dim3(8, 16, 4), 256, sm1>>>(poses);
    k2<<<dim3(8, 16), 256, sm2>>>();
    k34<<<dim3(16, 16), 256, sm34>>>(out);
}

// round 5
// speedup vs baseline: 2.4189x; 1.4121x over previous
#include <cuda_runtime.h>
#include <cuda_bf16.h>

#define EPSV 1e-5f

// ---------------- device scratch ----------------
// W1 tiles: [it=(dt*4+rc) 36][mt 17][16 rows][24 cols] bf16-bits
__device__ __align__(16) unsigned short g_W1h[36 * 17 * 16 * 24];
__device__ __align__(16) unsigned short g_W1l[36 * 17 * 16 * 24];
// W2 tiles: [it=(cc*9+dt) 153][mt 6][16 rows][24 cols]
__device__ __align__(16) unsigned short g_W2h[153 * 6 * 16 * 24];
__device__ __align__(16) unsigned short g_W2l[153 * 6 * 16 * 24];
__device__ float g_B1[272];
__device__ float g_B2[96];
__device__ float g_W3[16 * 480];
__device__ float g_B3[16];
__device__ float g_W4t[48 * 64];     // transposed: [k=c*3+dk][o]
__device__ float g_B4[64];
// split poses image: [n][t][64 cols pad] bf16-bits
__device__ __align__(16) unsigned short g_Ph[16 * 2048 * 64];
__device__ __align__(16) unsigned short g_Pl[16 * 2048 * 64];
// f1 split bf16: [n][ch=272][t]
__device__ __align__(16) unsigned short g_f1h[16 * 272 * 2048];
__device__ __align__(16) unsigned short g_f1l[16 * 272 * 2048];
// f2 fp32: [n][ch=96][t]
__device__ float g_f2[16 * 96 * 2048];

__constant__ int c_part_of[17] = {1,2,3,1,1,4,4,5,5,2,2,3,3,0,0,0,0};
__constant__ int c_idx_of[17]  = {0,0,0,1,2,0,1,0,1,1,2,1,2,0,1,2,3};
__constant__ int c_len_of[6]   = {4,3,3,3,2,2};

// ---------------- helpers ----------------
__device__ __forceinline__ void split_bf16(float x, unsigned short& h, unsigned short& l) {
    __nv_bfloat16 bh = __float2bfloat16(x);
    float r = x - __bfloat162float(bh);
    __nv_bfloat16 bl = __float2bfloat16(r);
    h = __bfloat16_as_ushort(bh);
    l = __bfloat16_as_ushort(bl);
}

__device__ __forceinline__ void ldsm4(unsigned r[4], const void* p) {
    unsigned a = (unsigned)__cvta_generic_to_shared(p);
    asm volatile("ldmatrix.sync.aligned.m8n8.x4.shared.b16 {%0,%1,%2,%3},[%4];"
                 : "=r"(r[0]), "=r"(r[1]), "=r"(r[2]), "=r"(r[3]) : "r"(a));
}

__device__ __forceinline__ void mma_bf16(float* c, const unsigned* a, unsigned b0, unsigned b1) {
    asm volatile("mma.sync.aligned.m16n8k16.row.col.f32.bf16.bf16.f32 "
                 "{%0,%1,%2,%3},{%4,%5,%6,%7},{%8,%9},{%0,%1,%2,%3};"
                 : "+f"(c[0]), "+f"(c[1]), "+f"(c[2]), "+f"(c[3])
                 : "r"(a[0]), "r"(a[1]), "r"(a[2]), "r"(a[3]), "r"(b0), "r"(b1));
}

__device__ __forceinline__ void cpa16(void* dst, const void* src) {
    unsigned d = (unsigned)__cvta_generic_to_shared(dst);
    asm volatile("cp.async.cg.shared.global [%0], [%1], 16;" :: "r"(d), "l"(src));
}
__device__ __forceinline__ void cpa16z(void* dst, const void* src, bool valid) {
    unsigned d = (unsigned)__cvta_generic_to_shared(dst);
    int sz = valid ? 16 : 0;
    asm volatile("cp.async.cg.shared.global [%0], [%1], 16, %2;" :: "r"(d), "l"(src), "r"(sz));
}
#define CP_COMMIT() asm volatile("cp.async.commit_group;")
#define CP_WAIT0()  asm volatile("cp.async.wait_group 0;")

// ---------------- prep: split poses to padded [n][t][64] ----------------
__global__ void prepPoses(const float* __restrict__ poses) {
    const int n = blockIdx.y, tb = blockIdx.x * 128;
    for (int idx = threadIdx.x; idx < 128 * 64; idx += blockDim.x) {
        int tl = idx >> 6, col = idx & 63;
        int t = tb + tl;
        float v = (col < 51) ? poses[((size_t)n * 2048 + t) * 51 + col] : 0.f;
        unsigned short h, l;
        split_bf16(v, h, l);
        size_t o = ((size_t)n * 2048 + t) * 64 + col;
        g_Ph[o] = h; g_Pl[o] = l;
    }
}

// ---------------- prep: fold + split + tile W1 ----------------
__global__ void prep1(const float* __restrict__ A1, const float* __restrict__ w1,
                      const float* __restrict__ b1, const float* __restrict__ g1,
                      const float* __restrict__ be1, const float* __restrict__ m1,
                      const float* __restrict__ v1) {
    int cw = blockIdx.x;               // 0..271
    int c = cw / 17, w = cw % 17;
    int mt = cw >> 4, row = cw & 15;
    float s = g1[cw] * rsqrtf(v1[cw] + EPSV);
    for (int e = threadIdx.x; e < 36 * 24; e += blockDim.x) {
        int it = e / 24, col = e % 24;      // it = dt*4+rc
        int dt = it >> 2, rc = it & 3;
        int r = rc * 16 + col;
        float val = 0.f;
        if (col < 16 && r < 51) {
            int u = r / 3, ci = r % 3;
            for (int k = 0; k < 5; k++)
                for (int dv = 0; dv < 5; dv++) {
                    int v = u - dv + 2;
                    if (v >= 0 && v < 17)
                        val += A1[(k * 17 + v) * 17 + w] *
                               w1[(((k * 16 + c) * 3 + ci) * 9 + dt) * 5 + dv];
                }
            val *= s;
        }
        unsigned short h, l;
        split_bf16(val, h, l);
        int idx = ((it * 17 + mt) * 16 + row) * 24 + col;
        g_W1h[idx] = h; g_W1l[idx] = l;
    }
    if (threadIdx.x == 0) {
        float bias = 0.f;
        for (int k = 0; k < 5; k++) {
            float sa = 0.f;
            for (int v = 0; v < 17; v++) sa += A1[(k * 17 + v) * 17 + w];
            bias += b1[k * 16 + c] * sa;
        }
        g_B1[cw] = (bias - m1[cw]) * s + be1[cw];
    }
}

// ---------------- prep: fold + split + tile W2 ----------------
__global__ void prep2(const float* __restrict__ A2, const float* __restrict__ w2,
                      const float* __restrict__ b2, const float* __restrict__ g2,
                      const float* __restrict__ be2, const float* __restrict__ m2,
                      const float* __restrict__ v2) {
    int cw = blockIdx.x;               // 0..95
    int c = cw / 6, w = cw % 6;
    int mt = cw >> 4, row = cw & 15;
    float s = g2[cw] * rsqrtf(v2[cw] + EPSV);
    for (int e = threadIdx.x; e < 153 * 24; e += blockDim.x) {
        int it = e / 24, col = e % 24;      // it = cc*9+dt
        int cc = it / 9, dt = it % 9;
        int ch = cc * 16 + col;
        float val = 0.f;
        if (col < 16) {
            int f = ch / 17, jt = ch % 17;
            int p = c_part_of[jt], j = c_idx_of[jt], ln = c_len_of[p];
            int ci = f * ln + j;
            for (int k = 0; k < 5; k++)
                for (int v = 0; v < 6; v++) {
                    int dp = p - v + 1;
                    if (dp >= 0 && dp < 3)
                        val += A2[(k * 6 + v) * 6 + w] *
                               w2[(((k * 16 + c) * 64 + ci) * 9 + dt) * 3 + dp];
                }
            val *= s;
        }
        unsigned short h, l;
        split_bf16(val, h, l);
        int idx = ((it * 6 + mt) * 16 + row) * 24 + col;
        g_W2h[idx] = h; g_W2l[idx] = l;
    }
    if (threadIdx.x == 0) {
        float bias = 0.f;
        for (int k = 0; k < 5; k++) {
            float sa = 0.f;
            for (int v = 0; v < 6; v++) sa += A2[(k * 6 + v) * 6 + w];
            bias += b2[k * 16 + c] * sa;
        }
        g_B2[cw] = (bias - m2[cw]) * s + be2[cw];
    }
}

__global__ void prep34(const float* __restrict__ w3, const float* __restrict__ b3,
                       const float* __restrict__ g3, const float* __restrict__ be3,
                       const float* __restrict__ m3, const float* __restrict__ v3,
                       const float* __restrict__ w4, const float* __restrict__ b4,
                       const float* __restrict__ g4, const float* __restrict__ be4,
                       const float* __restrict__ m4, const float* __restrict__ v4) {
    for (int e = threadIdx.x; e < 7680; e += blockDim.x) {
        int o = e / 480;
        g_W3[e] = w3[e] * (g3[o] * rsqrtf(v3[o] + EPSV));
    }
    for (int e = threadIdx.x; e < 3072; e += blockDim.x) {
        int o = e / 48, k = e % 48;
        g_W4t[k * 64 + o] = w4[e] * (g4[o] * rsqrtf(v4[o] + EPSV));
    }
    if (threadIdx.x < 16) {
        int o = threadIdx.x;
        float s = g3[o] * rsqrtf(v3[o] + EPSV);
        g_B3[o] = (b3[o] - m3[o]) * s + be3[o];
    }
    if (threadIdx.x >= 32 && threadIdx.x < 96) {
        int o = threadIdx.x - 32;
        float s = g4[o] * rsqrtf(v4[o] + EPSV);
        g_B4[o] = (b4[o] - m4[o]) * s + be4[o];
    }
}

// ---------------- stage 1 tensor GEMM (dt-factored, single-sync pipeline) ----------------
// grid (8 tTiles [N=256], 16 n, 4 mQuarters). 256 thr.
// smem: Wbuf0 7680 | Wbuf1 7680 | Xh 38016 | Xl 38016 = 91392 B
#define K1_XOFF 15360
#define K1_XSZ  38016
__global__ void __launch_bounds__(256) k1() {
    extern __shared__ char sm[];
    const int n = blockIdx.y, t0 = blockIdx.x * 256;
    const int z = blockIdx.z;
    const int mt0 = (z == 0) ? 0 : 1 + z * 4;          // 0,5,9,13
    const int mcount = (z == 0) ? 5 : 4;
    const int tid = threadIdx.x, lane = tid & 31, w = tid >> 5;

    char* Xh = sm + K1_XOFF;
    char* Xl = sm + K1_XOFF + K1_XSZ;

    auto prefW = [&](int it, char* buf) {
        const char* srcH = (const char*)(g_W1h + (size_t)(it * 17 + mt0) * 384);
        const char* srcL = (const char*)(g_W1l + (size_t)(it * 17 + mt0) * 384);
        int cnt = mcount * 48;
        for (int i = tid; i < cnt; i += 256) {
            cpa16(buf + i * 16, srcH + i * 16);
            cpa16(buf + 3840 + i * 16, srcL + i * 16);
        }
    };

    // initial group: whole X tile via cp.async (+zfill halo) + W(it=0)
    for (int i = tid; i < 264 * 8; i += 256) {
        int row = i >> 3, q = i & 7;
        int t = t0 - 4 + row;
        bool valid = (t >= 0 && t < 2048);
        size_t so = ((size_t)n * 2048 + (valid ? t : 0)) * 64 + q * 8;
        cpa16z(Xh + row * 144 + q * 16, g_Ph + so, valid);
        cpa16z(Xl + row * 144 + q * 16, g_Pl + so, valid);
    }
    prefW(0, sm);
    CP_COMMIT();

    float C[5][4][4];
#pragma unroll
    for (int i = 0; i < 5; i++)
#pragma unroll
        for (int j = 0; j < 4; j++)
#pragma unroll
            for (int q = 0; q < 4; q++) C[i][j][q] = 0.f;

    const int lrow = (lane & 15) * 48 + (lane >> 4) * 16;

    for (int it = 0; it < 36; it++) {
        char* buf = sm + (it & 1) * 7680;
        CP_WAIT0();
        __syncthreads();
        if (it + 1 < 36) { prefW(it + 1, sm + ((it + 1) & 1) * 7680); CP_COMMIT(); }

        const int dt = it >> 2, rc = it & 3;
        const int colb = (rc * 16 + (lane & 3) * 2) * 2;
        unsigned bh[4][2], bl[4][2];
#pragma unroll
        for (int nb = 0; nb < 4; nb++) {
            int tt = w * 32 + nb * 8 + (lane >> 2) + dt;
            const char* ph = Xh + tt * 144 + colb;
            const char* pl = Xl + tt * 144 + colb;
            bh[nb][0] = *(const unsigned*)ph; bh[nb][1] = *(const unsigned*)(ph + 16);
            bl[nb][0] = *(const unsigned*)pl; bl[nb][1] = *(const unsigned*)(pl + 16);
        }
        for (int mi = 0; mi < mcount; mi++) {
            unsigned Ah[4], Al[4];
            ldsm4(Ah, buf + mi * 768 + lrow);
            ldsm4(Al, buf + 3840 + mi * 768 + lrow);
#pragma unroll
            for (int nb = 0; nb < 4; nb++) {
                mma_bf16(C[mi][nb], Ah, bh[nb][0], bh[nb][1]);
                mma_bf16(C[mi][nb], Ah, bl[nb][0], bl[nb][1]);
                mma_bf16(C[mi][nb], Al, bh[nb][0], bh[nb][1]);
            }
        }
    }

    // epilogue: bias + split store  (f1 layout [n][ch][t])
    for (int mi = 0; mi < mcount; mi++) {
#pragma unroll
        for (int nb = 0; nb < 4; nb++) {
            int ch0 = (mt0 + mi) * 16 + (lane >> 2);
            int tt = t0 + w * 32 + nb * 8 + (lane & 3) * 2;
            float b0 = g_B1[ch0], b1 = g_B1[ch0 + 8];
            unsigned short h0, l0, h1, l1;
            size_t o0 = ((size_t)n * 272 + ch0) * 2048 + tt;
            split_bf16(C[mi][nb][0] + b0, h0, l0);
            split_bf16(C[mi][nb][1] + b0, h1, l1);
            *(unsigned*)&g_f1h[o0] = (unsigned)h0 | ((unsigned)h1 << 16);
            *(unsigned*)&g_f1l[o0] = (unsigned)l0 | ((unsigned)l1 << 16);
            size_t o1 = ((size_t)n * 272 + ch0 + 8) * 2048 + tt;
            split_bf16(C[mi][nb][2] + b1, h0, l0);
            split_bf16(C[mi][nb][3] + b1, h1, l1);
            *(unsigned*)&g_f1h[o1] = (unsigned)h0 | ((unsigned)h1 << 16);
            *(unsigned*)&g_f1l[o1] = (unsigned)l0 | ((unsigned)l1 << 16);
        }
    }
}

// ---------------- stage 2 tensor GEMM (dt-factored, X double-buffered) ----------------
// grid (8 tTiles [N=256], 16 n). 256 thr. K = 17 cc x 9 dt.
// smem: Wbuf 2x9216 | X 2x(12672+12672) = 69120 B
#define K2_WSZ 18432
#define K2_XB  25344
__global__ void __launch_bounds__(256) k2() {
    extern __shared__ char sm[];
    const int n = blockIdx.y, t0 = blockIdx.x * 256;
    const int tid = threadIdx.x, lane = tid & 31, w = tid >> 5;
    const int g = tid & 15, jj = tid >> 4;     // staging: g = channel, jj = t-pair group

    unsigned sh[9], sl[9];

    auto prefW = [&](int it, char* buf) {
        const char* srcH = (const char*)(g_W2h + (size_t)it * 2304);
        const char* srcL = (const char*)(g_W2l + (size_t)it * 2304);
        for (int i = tid; i < 288; i += 256) {
            cpa16(buf + i * 16, srcH + i * 16);
            cpa16(buf + 4608 + i * 16, srcL + i * 16);
        }
    };
    auto loadX = [&](int cc) {   // LDG stage cc's X into regs (t-pairs)
        size_t base = ((size_t)n * 272 + cc * 16 + g) * 2048;
#pragma unroll
        for (int i = 0; i < 9; i++) {
            int p = jj + 16 * i;
            sh[i] = 0; sl[i] = 0;
            if (p < 132) {
                int t = t0 - 4 + 2 * p;
                if (t >= 0 && t < 2048) {
                    sh[i] = *(const unsigned*)(g_f1h + base + t);
                    sl[i] = *(const unsigned*)(g_f1l + base + t);
                }
            }
        }
    };
    auto stsX = [&](int buf) {
        unsigned short* Xh = (unsigned short*)(sm + K2_WSZ + buf * K2_XB);
        unsigned short* Xl = (unsigned short*)(sm + K2_WSZ + buf * K2_XB + 12672);
#pragma unroll
        for (int i = 0; i < 9; i++) {
            int p = jj + 16 * i;
            if (p < 132) {
                Xh[(2 * p) * 24 + g] = (unsigned short)(sh[i] & 0xffff);
                Xh[(2 * p + 1) * 24 + g] = (unsigned short)(sh[i] >> 16);
                Xl[(2 * p) * 24 + g] = (unsigned short)(sl[i] & 0xffff);
                Xl[(2 * p + 1) * 24 + g] = (unsigned short)(sl[i] >> 16);
            }
        }
    };

    // preload X(0) + W(0)
    loadX(0);
    stsX(0);
    prefW(0, sm);
    CP_COMMIT();

    float C[6][4][4];
#pragma unroll
    for (int i = 0; i < 6; i++)
#pragma unroll
        for (int j = 0; j < 4; j++)
#pragma unroll
            for (int q = 0; q < 4; q++) C[i][j][q] = 0.f;

    const int lrow = (lane & 15) * 48 + (lane >> 4) * 16;
    const int colb = ((lane & 3) * 2) * 2;

    for (int it = 0; it < 153; it++) {
        const int cc = it / 9, dt = it - cc * 9;
        char* buf = sm + (it & 1) * 9216;
        CP_WAIT0();
        __syncthreads();
        if (it + 1 < 153) { prefW(it + 1, sm + ((it + 1) & 1) * 9216); CP_COMMIT(); }
        if (dt == 0 && cc < 16) loadX(cc + 1);
        if (dt == 7 && cc < 16) stsX((cc + 1) & 1);

        const char* Xh = sm + K2_WSZ + (cc & 1) * K2_XB;
        const char* Xl = Xh + 12672;
        unsigned bh[4][2], bl[4][2];
#pragma unroll
        for (int nb = 0; nb < 4; nb++) {
            int tt = w * 32 + nb * 8 + (lane >> 2) + dt;
            const char* ph = Xh + tt * 48 + colb;
            const char* pl = Xl + tt * 48 + colb;
            bh[nb][0] = *(const unsigned*)ph; bh[nb][1] = *(const unsigned*)(ph + 16);
            bl[nb][0] = *(const unsigned*)pl; bl[nb][1] = *(const unsigned*)(pl + 16);
        }
#pragma unroll
        for (int mi = 0; mi < 6; mi++) {
            unsigned Ah[4], Al[4];
            ldsm4(Ah, buf + mi * 768 + lrow);
            ldsm4(Al, buf + 4608 + mi * 768 + lrow);
#pragma unroll
            for (int nb = 0; nb < 4; nb++) {
                mma_bf16(C[mi][nb], Ah, bh[nb][0], bh[nb][1]);
                mma_bf16(C[mi][nb], Ah, bl[nb][0], bl[nb][1]);
                mma_bf16(C[mi][nb], Al, bh[nb][0], bh[nb][1]);
            }
        }
    }

    // epilogue: bias + fp32 store [ch][t]
#pragma unroll
    for (int mi = 0; mi < 6; mi++) {
#pragma unroll
        for (int nb = 0; nb < 4; nb++) {
            int ch0 = mi * 16 + (lane >> 2);
            int tt = t0 + w * 32 + nb * 8 + (lane & 3) * 2;
            float b0 = g_B2[ch0], b1 = g_B2[ch0 + 8];
            float2 v0 = make_float2(C[mi][nb][0] + b0, C[mi][nb][1] + b0);
            float2 v1 = make_float2(C[mi][nb][2] + b1, C[mi][nb][3] + b1);
            *(float2*)&g_f2[((size_t)n * 96 + ch0) * 2048 + tt] = v0;
            *(float2*)&g_f2[((size_t)n * 96 + ch0 + 8) * 2048 + tt] = v1;
        }
    }
}

// ---------------- stages 3+4 fused (register-blocked) ----------------
__global__ void __launch_bounds__(256) k34(float* __restrict__ out) {
    extern __shared__ float smf[];
    float* F2s = smf;                    // [96][136]  (t halo -3..)
    float* F3s = F2s + 96 * 136;         // [16][132]
    float* W3s = F3s + 16 * 132;         // 7680
    float* W4s = W3s + 7680;             // 3072 (transposed [48][64])
    const int n = blockIdx.y;
    const int t0 = blockIdx.x * 128;
    const int tid = threadIdx.x;

    for (int idx = tid; idx < 96 * 136; idx += 256) {
        int c = idx / 136, q = idx - c * 136;
        int t = t0 - 3 + q;
        F2s[idx] = (t >= 0 && t < 2048) ? g_f2[((size_t)n * 96 + c) * 2048 + t] : 0.f;
    }
    for (int idx = tid; idx < 7680; idx += 256) W3s[idx] = g_W3[idx];
    for (int idx = tid; idx < 3072; idx += 256) W4s[idx] = g_W4t[idx];
    __syncthreads();

    // f3: units (o 0..15, q 0..32) of 4 tp each
    for (int idx = tid; idx < 16 * 33; idx += 256) {
        int o = idx / 33, q = idx - 33 * (idx / 33);
        int tp0 = 4 * q;
        float bb = g_B3[o];
        float acc[4] = {bb, bb, bb, bb};
        const float* wr = W3s + o * 480;
        for (int c = 0; c < 96; c++) {
            float4 A = *(const float4*)(F2s + c * 136 + tp0);
            float4 Bv = *(const float4*)(F2s + c * 136 + tp0 + 4);
            float f[8] = {A.x, A.y, A.z, A.w, Bv.x, Bv.y, Bv.z, Bv.w};
#pragma unroll
            for (int dk = 0; dk < 5; dk++) {
                float wv = wr[c * 5 + dk];
#pragma unroll
                for (int j = 0; j < 4; j++) acc[j] = fmaf(wv, f[j + dk], acc[j]);
            }
        }
#pragma unroll
        for (int j = 0; j < 4; j++) {
            int tp = tp0 + j;
            int t3 = t0 - 1 + tp;
            float v = 0.f;
            if (tp < 130 && t3 >= 0 && t3 < 2048)
                v = acc[j] > 0.f ? acc[j] : 0.01f * acc[j];
            F3s[o * 132 + tp] = v;
        }
    }
    __syncthreads();

    // f4: units (tl-block of 4? no: tl scalar, o-quad): idx -> tl = idx&127, o0 = (idx>>7)*4
#pragma unroll
    for (int u = 0; u < 8; u++) {
        int idx = tid + u * 256;
        int tl = idx & 127, o0 = (idx >> 7) * 4;
        float acc[4];
#pragma unroll
        for (int i = 0; i < 4; i++) acc[i] = g_B4[o0 + i];
        for (int c = 0; c < 16; c++) {
            float f0 = F3s[c * 132 + tl];
            float f1 = F3s[c * 132 + tl + 1];
            float f2v = F3s[c * 132 + tl + 2];
            float fv[3] = {f0, f1, f2v};
#pragma unroll
            for (int dk = 0; dk < 3; dk++) {
                float4 wv = *(const float4*)(W4s + (c * 3 + dk) * 64 + o0);
                acc[0] = fmaf(wv.x, fv[dk], acc[0]);
                acc[1] = fmaf(wv.y, fv[dk], acc[1]);
                acc[2] = fmaf(wv.z, fv[dk], acc[2]);
                acc[3] = fmaf(wv.w, fv[dk], acc[3]);
            }
        }
        float4 r;
        r.x = acc[0] > 0.f ? acc[0] : 0.01f * acc[0];
        r.y = acc[1] > 0.f ? acc[1] : 0.01f * acc[1];
        r.z = acc[2] > 0.f ? acc[2] : 0.01f * acc[2];
        r.w = acc[3] > 0.f ? acc[3] : 0.01f * acc[3];
        *(float4*)&out[((size_t)n * 2048 + t0 + tl) * 64 + o0] = r;
    }
}

// ---------------- launch ----------------
extern "C" void kernel_launch(void* const* d_in, const int* in_sizes, int n_in,
                              void* d_out, int out_size) {
    (void)in_sizes; (void)n_in; (void)out_size;
    const float* poses = (const float*)d_in[0];
    const float* A1 = (const float*)d_in[1];
    const float* A2 = (const float*)d_in[2];
    const float* w1 = (const float*)d_in[3];
    const float* b1 = (const float*)d_in[4];
    const float* g1 = (const float*)d_in[5];
    const float* be1 = (const float*)d_in[6];
    const float* m1 = (const float*)d_in[7];
    const float* v1 = (const float*)d_in[8];
    const float* w2 = (const float*)d_in[9];
    const float* b2 = (const float*)d_in[10];
    const float* g2 = (const float*)d_in[11];
    const float* be2 = (const float*)d_in[12];
    const float* m2 = (const float*)d_in[13];
    const float* v2 = (const float*)d_in[14];
    const float* w3 = (const float*)d_in[15];
    const float* b3 = (const float*)d_in[16];
    const float* g3 = (const float*)d_in[17];
    const float* be3 = (const float*)d_in[18];
    const float* m3 = (const float*)d_in[19];
    const float* v3 = (const float*)d_in[20];
    const float* w4 = (const float*)d_in[21];
    const float* b4 = (const float*)d_in[22];
    const float* g4 = (const float*)d_in[23];
    const float* be4 = (const float*)d_in[24];
    const float* m4 = (const float*)d_in[25];
    const float* v4 = (const float*)d_in[26];
    float* out = (float*)d_out;

    size_t sm1 = 91392;
    size_t sm2 = 69120;
    size_t sm34 = (96 * 136 + 16 * 132 + 7680 + 3072) * sizeof(float);  // 103680
    cudaFuncSetAttribute(k1, cudaFuncAttributeMaxDynamicSharedMemorySize, (int)sm1);
    cudaFuncSetAttribute(k2, cudaFuncAttributeMaxDynamicSharedMemorySize, (int)sm2);
    cudaFuncSetAttribute(k34, cudaFuncAttributeMaxDynamicSharedMemorySize, (int)sm34);

    prepPoses<<<dim3(16, 16), 256>>>(poses);
    prep1<<<272, 256>>>(A1, w1, b1, g1, be1, m1, v1);
    prep2<<<96, 256>>>(A2, w2, b2, g2, be2, m2, v2);
    prep34<<<1, 512>>>(w3, b3, g3, be3, m3, v3, w4, b4, g4, be4, m4, v4);
    k1<<<dim3(8, 16, 4), 256, sm1>>>();
    k2<<<dim3(8, 16), 256, sm2>>>();
    k34<<<dim3(16, 16), 256, sm34>>>(out);
}

// round 6
// speedup vs baseline: 2.5815x; 1.0672x over previous
#include <cuda_runtime.h>
#include <cuda_bf16.h>

#define EPSV 1e-5f

// ---------------- device scratch ----------------
__device__ __align__(16) unsigned short g_W1h[36 * 17 * 16 * 24];
__device__ __align__(16) unsigned short g_W1l[36 * 17 * 16 * 24];
__device__ __align__(16) unsigned short g_W2h[153 * 6 * 16 * 24];
__device__ __align__(16) unsigned short g_W2l[153 * 6 * 16 * 24];
__device__ float g_B1[272];
__device__ float g_B2[96];
__device__ float g_W3[16 * 480];
__device__ float g_B3[16];
__device__ float g_W4t[48 * 64];     // transposed: [k=c*3+dk][o]
__device__ float g_B4[64];
__device__ __align__(16) unsigned short g_Ph[16 * 2048 * 64];
__device__ __align__(16) unsigned short g_Pl[16 * 2048 * 64];
__device__ __align__(16) unsigned short g_f1h[16 * 272 * 2048];
__device__ __align__(16) unsigned short g_f1l[16 * 272 * 2048];
__device__ float g_f2[16 * 96 * 2048];    // K-split partial 0 (with bias)
__device__ float g_f2b[16 * 96 * 2048];   // K-split partial 1

__constant__ int c_part_of[17] = {1,2,3,1,1,4,4,5,5,2,2,3,3,0,0,0,0};
__constant__ int c_idx_of[17]  = {0,0,0,1,2,0,1,0,1,1,2,1,2,0,1,2,3};
__constant__ int c_len_of[6]   = {4,3,3,3,2,2};

// ---------------- helpers ----------------
__device__ __forceinline__ void split_bf16(float x, unsigned short& h, unsigned short& l) {
    __nv_bfloat16 bh = __float2bfloat16(x);
    float r = x - __bfloat162float(bh);
    __nv_bfloat16 bl = __float2bfloat16(r);
    h = __bfloat16_as_ushort(bh);
    l = __bfloat16_as_ushort(bl);
}

__device__ __forceinline__ void ldsm4(unsigned r[4], const void* p) {
    unsigned a = (unsigned)__cvta_generic_to_shared(p);
    asm volatile("ldmatrix.sync.aligned.m8n8.x4.shared.b16 {%0,%1,%2,%3},[%4];"
                 : "=r"(r[0]), "=r"(r[1]), "=r"(r[2]), "=r"(r[3]) : "r"(a));
}

__device__ __forceinline__ void mma_bf16(float* c, const unsigned* a, unsigned b0, unsigned b1) {
    asm volatile("mma.sync.aligned.m16n8k16.row.col.f32.bf16.bf16.f32 "
                 "{%0,%1,%2,%3},{%4,%5,%6,%7},{%8,%9},{%0,%1,%2,%3};"
                 : "+f"(c[0]), "+f"(c[1]), "+f"(c[2]), "+f"(c[3])
                 : "r"(a[0]), "r"(a[1]), "r"(a[2]), "r"(a[3]), "r"(b0), "r"(b1));
}

__device__ __forceinline__ void cpa16(void* dst, const void* src) {
    unsigned d = (unsigned)__cvta_generic_to_shared(dst);
    asm volatile("cp.async.cg.shared.global [%0], [%1], 16;" :: "r"(d), "l"(src));
}
__device__ __forceinline__ void cpa16z(void* dst, const void* src, bool valid) {
    unsigned d = (unsigned)__cvta_generic_to_shared(dst);
    int sz = valid ? 16 : 0;
    asm volatile("cp.async.cg.shared.global [%0], [%1], 16, %2;" :: "r"(d), "l"(src), "r"(sz));
}
#define CP_COMMIT() asm volatile("cp.async.commit_group;")
#define CP_WAIT0()  asm volatile("cp.async.wait_group 0;")

// ---------------- single fused prep kernel (656 blocks x 256 thr) ----------------
__global__ void prepAll(const float* __restrict__ poses,
                        const float* __restrict__ A1, const float* __restrict__ w1,
                        const float* __restrict__ b1, const float* __restrict__ g1,
                        const float* __restrict__ be1, const float* __restrict__ m1,
                        const float* __restrict__ v1,
                        const float* __restrict__ A2, const float* __restrict__ w2,
                        const float* __restrict__ b2, const float* __restrict__ g2,
                        const float* __restrict__ be2, const float* __restrict__ m2,
                        const float* __restrict__ v2,
                        const float* __restrict__ w3, const float* __restrict__ b3,
                        const float* __restrict__ g3, const float* __restrict__ be3,
                        const float* __restrict__ m3, const float* __restrict__ v3,
                        const float* __restrict__ w4, const float* __restrict__ b4,
                        const float* __restrict__ g4, const float* __restrict__ be4,
                        const float* __restrict__ m4, const float* __restrict__ v4) {
    const int bid = blockIdx.x;
    if (bid < 256) {
        // ---- poses split ----
        const int n = bid >> 4, tb = (bid & 15) * 128;
        for (int idx = threadIdx.x; idx < 128 * 64; idx += 256) {
            int tl = idx >> 6, col = idx & 63;
            int t = tb + tl;
            float v = (col < 51) ? poses[((size_t)n * 2048 + t) * 51 + col] : 0.f;
            unsigned short h, l;
            split_bf16(v, h, l);
            size_t o = ((size_t)n * 2048 + t) * 64 + col;
            g_Ph[o] = h; g_Pl[o] = l;
        }
    } else if (bid < 528) {
        // ---- W1 fold ----
        int cw = bid - 256;
        int c = cw / 17, w = cw % 17;
        int mt = cw >> 4, row = cw & 15;
        float s = g1[cw] * rsqrtf(v1[cw] + EPSV);
        for (int e = threadIdx.x; e < 36 * 24; e += 256) {
            int it = e / 24, col = e % 24;
            int dt = it >> 2, rc = it & 3;
            int r = rc * 16 + col;
            float val = 0.f;
            if (col < 16 && r < 51) {
                int u = r / 3, ci = r % 3;
                for (int k = 0; k < 5; k++)
                    for (int dv = 0; dv < 5; dv++) {
                        int v = u - dv + 2;
                        if (v >= 0 && v < 17)
                            val += A1[(k * 17 + v) * 17 + w] *
                                   w1[(((k * 16 + c) * 3 + ci) * 9 + dt) * 5 + dv];
                    }
                val *= s;
            }
            unsigned short h, l;
            split_bf16(val, h, l);
            int idx = ((it * 17 + mt) * 16 + row) * 24 + col;
            g_W1h[idx] = h; g_W1l[idx] = l;
        }
        if (threadIdx.x == 0) {
            float bias = 0.f;
            for (int k = 0; k < 5; k++) {
                float sa = 0.f;
                for (int v = 0; v < 17; v++) sa += A1[(k * 17 + v) * 17 + w];
                bias += b1[k * 16 + c] * sa;
            }
            g_B1[cw] = (bias - m1[cw]) * s + be1[cw];
        }
    } else if (bid < 624) {
        // ---- W2 fold ----
        int cw = bid - 528;
        int c = cw / 6, w = cw % 6;
        int mt = cw >> 4, row = cw & 15;
        float s = g2[cw] * rsqrtf(v2[cw] + EPSV);
        for (int e = threadIdx.x; e < 153 * 24; e += 256) {
            int it = e / 24, col = e % 24;
            int cc = it / 9, dt = it % 9;
            int ch = cc * 16 + col;
            float val = 0.f;
            if (col < 16) {
                int f = ch / 17, jt = ch % 17;
                int p = c_part_of[jt], j = c_idx_of[jt], ln = c_len_of[p];
                int ci = f * ln + j;
                for (int k = 0; k < 5; k++)
                    for (int v = 0; v < 6; v++) {
                        int dp = p - v + 1;
                        if (dp >= 0 && dp < 3)
                            val += A2[(k * 6 + v) * 6 + w] *
                                   w2[(((k * 16 + c) * 64 + ci) * 9 + dt) * 3 + dp];
                    }
                val *= s;
            }
            unsigned short h, l;
            split_bf16(val, h, l);
            int idx = ((it * 6 + mt) * 16 + row) * 24 + col;
            g_W2h[idx] = h; g_W2l[idx] = l;
        }
        if (threadIdx.x == 0) {
            float bias = 0.f;
            for (int k = 0; k < 5; k++) {
                float sa = 0.f;
                for (int v = 0; v < 6; v++) sa += A2[(k * 6 + v) * 6 + w];
                bias += b2[k * 16 + c] * sa;
            }
            g_B2[cw] = (bias - m2[cw]) * s + be2[cw];
        }
    } else {
        // ---- W3 / W4 fold (32 blocks, strided) ----
        int base = (bid - 624) * 256 + threadIdx.x;   // stride 8192 covers all in 1 pass
        if (base < 7680) {
            int o = base / 480;
            g_W3[base] = w3[base] * (g3[o] * rsqrtf(v3[o] + EPSV));
        }
        if (base < 3072) {
            int o = base / 48, k = base % 48;
            g_W4t[k * 64 + o] = w4[base] * (g4[o] * rsqrtf(v4[o] + EPSV));
        }
        if (base < 16) {
            float s = g3[base] * rsqrtf(v3[base] + EPSV);
            g_B3[base] = (b3[base] - m3[base]) * s + be3[base];
        }
        if (base >= 32 && base < 96) {
            int o = base - 32;
            float s = g4[o] * rsqrtf(v4[o] + EPSV);
            g_B4[o] = (b4[o] - m4[o]) * s + be4[o];
        }
    }
}

// ---------------- stage 1 tensor GEMM (dt-factored, single-sync pipeline) ----------------
#define K1_XOFF 15360
#define K1_XSZ  38016
__global__ void __launch_bounds__(256, 2) k1() {
    extern __shared__ char sm[];
    const int n = blockIdx.y, t0 = blockIdx.x * 256;
    const int z = blockIdx.z;
    const int mt0 = (z == 0) ? 0 : 1 + z * 4;          // 0,5,9,13
    const int mcount = (z == 0) ? 5 : 4;
    const int tid = threadIdx.x, lane = tid & 31, w = tid >> 5;

    char* Xh = sm + K1_XOFF;
    char* Xl = sm + K1_XOFF + K1_XSZ;

    auto prefW = [&](int it, char* buf) {
        const char* srcH = (const char*)(g_W1h + (size_t)(it * 17 + mt0) * 384);
        const char* srcL = (const char*)(g_W1l + (size_t)(it * 17 + mt0) * 384);
        int cnt = mcount * 48;
        for (int i = tid; i < cnt; i += 256) {
            cpa16(buf + i * 16, srcH + i * 16);
            cpa16(buf + 3840 + i * 16, srcL + i * 16);
        }
    };

    for (int i = tid; i < 264 * 8; i += 256) {
        int row = i >> 3, q = i & 7;
        int t = t0 - 4 + row;
        bool valid = (t >= 0 && t < 2048);
        size_t so = ((size_t)n * 2048 + (valid ? t : 0)) * 64 + q * 8;
        cpa16z(Xh + row * 144 + q * 16, g_Ph + so, valid);
        cpa16z(Xl + row * 144 + q * 16, g_Pl + so, valid);
    }
    prefW(0, sm);
    CP_COMMIT();

    float C[5][4][4];
#pragma unroll
    for (int i = 0; i < 5; i++)
#pragma unroll
        for (int j = 0; j < 4; j++)
#pragma unroll
            for (int q = 0; q < 4; q++) C[i][j][q] = 0.f;

    const int lrow = (lane & 15) * 48 + (lane >> 4) * 16;

    for (int it = 0; it < 36; it++) {
        char* buf = sm + (it & 1) * 7680;
        CP_WAIT0();
        __syncthreads();
        if (it + 1 < 36) { prefW(it + 1, sm + ((it + 1) & 1) * 7680); CP_COMMIT(); }

        const int dt = it >> 2, rc = it & 3;
        const int colb = (rc * 16 + (lane & 3) * 2) * 2;
        unsigned bh[4][2], bl[4][2];
#pragma unroll
        for (int nb = 0; nb < 4; nb++) {
            int tt = w * 32 + nb * 8 + (lane >> 2) + dt;
            const char* ph = Xh + tt * 144 + colb;
            const char* pl = Xl + tt * 144 + colb;
            bh[nb][0] = *(const unsigned*)ph; bh[nb][1] = *(const unsigned*)(ph + 16);
            bl[nb][0] = *(const unsigned*)pl; bl[nb][1] = *(const unsigned*)(pl + 16);
        }
        for (int mi = 0; mi < mcount; mi++) {
            unsigned Ah[4], Al[4];
            ldsm4(Ah, buf + mi * 768 + lrow);
            ldsm4(Al, buf + 3840 + mi * 768 + lrow);
#pragma unroll
            for (int nb = 0; nb < 4; nb++) {
                mma_bf16(C[mi][nb], Ah, bh[nb][0], bh[nb][1]);
                mma_bf16(C[mi][nb], Ah, bl[nb][0], bl[nb][1]);
                mma_bf16(C[mi][nb], Al, bh[nb][0], bh[nb][1]);
            }
        }
    }

    for (int mi = 0; mi < mcount; mi++) {
#pragma unroll
        for (int nb = 0; nb < 4; nb++) {
            int ch0 = (mt0 + mi) * 16 + (lane >> 2);
            int tt = t0 + w * 32 + nb * 8 + (lane & 3) * 2;
            float b0 = g_B1[ch0], b1 = g_B1[ch0 + 8];
            unsigned short h0, l0, h1, l1;
            size_t o0 = ((size_t)n * 272 + ch0) * 2048 + tt;
            split_bf16(C[mi][nb][0] + b0, h0, l0);
            split_bf16(C[mi][nb][1] + b0, h1, l1);
            *(unsigned*)&g_f1h[o0] = (unsigned)h0 | ((unsigned)h1 << 16);
            *(unsigned*)&g_f1l[o0] = (unsigned)l0 | ((unsigned)l1 << 16);
            size_t o1 = ((size_t)n * 272 + ch0 + 8) * 2048 + tt;
            split_bf16(C[mi][nb][2] + b1, h0, l0);
            split_bf16(C[mi][nb][3] + b1, h1, l1);
            *(unsigned*)&g_f1h[o1] = (unsigned)h0 | ((unsigned)h1 << 16);
            *(unsigned*)&g_f1l[o1] = (unsigned)l0 | ((unsigned)l1 << 16);
        }
    }
}

// ---------------- stage 2 tensor GEMM (dt-factored, K-split over z, X dbl-buffered) ----------------
// grid (8 tTiles, 16 n, 2 K-halves). z=0: cc 0..8 -> g_f2 (+bias); z=1: cc 9..16 -> g_f2b
#define K2_WSZ 18432
#define K2_XB  25344
__global__ void __launch_bounds__(256, 2) k2() {
    extern __shared__ char sm[];
    const int n = blockIdx.y, t0 = blockIdx.x * 256;
    const int zz = blockIdx.z;
    const int cc0 = zz ? 9 : 0;
    const int ncc = zz ? 8 : 9;
    const int tid = threadIdx.x, lane = tid & 31, w = tid >> 5;
    const int g = tid & 15, jj = tid >> 4;

    unsigned sh[9], sl[9];

    auto prefW = [&](int it, char* buf) {
        const char* srcH = (const char*)(g_W2h + (size_t)it * 2304);
        const char* srcL = (const char*)(g_W2l + (size_t)it * 2304);
        for (int i = tid; i < 288; i += 256) {
            cpa16(buf + i * 16, srcH + i * 16);
            cpa16(buf + 4608 + i * 16, srcL + i * 16);
        }
    };
    auto loadX = [&](int cc) {
        size_t base = ((size_t)n * 272 + cc * 16 + g) * 2048;
#pragma unroll
        for (int i = 0; i < 9; i++) {
            int p = jj + 16 * i;
            sh[i] = 0; sl[i] = 0;
            if (p < 132) {
                int t = t0 - 4 + 2 * p;
                if (t >= 0 && t < 2048) {
                    sh[i] = *(const unsigned*)(g_f1h + base + t);
                    sl[i] = *(const unsigned*)(g_f1l + base + t);
                }
            }
        }
    };
    auto stsX = [&](int buf) {
        unsigned short* Xh = (unsigned short*)(sm + K2_WSZ + buf * K2_XB);
        unsigned short* Xl = (unsigned short*)(sm + K2_WSZ + buf * K2_XB + 12672);
#pragma unroll
        for (int i = 0; i < 9; i++) {
            int p = jj + 16 * i;
            if (p < 132) {
                Xh[(2 * p) * 24 + g] = (unsigned short)(sh[i] & 0xffff);
                Xh[(2 * p + 1) * 24 + g] = (unsigned short)(sh[i] >> 16);
                Xl[(2 * p) * 24 + g] = (unsigned short)(sl[i] & 0xffff);
                Xl[(2 * p + 1) * 24 + g] = (unsigned short)(sl[i] >> 16);
            }
        }
    };

    loadX(cc0);
    stsX(0);
    prefW(cc0 * 9, sm);
    CP_COMMIT();

    float C[6][4][4];
#pragma unroll
    for (int i = 0; i < 6; i++)
#pragma unroll
        for (int j = 0; j < 4; j++)
#pragma unroll
            for (int q = 0; q < 4; q++) C[i][j][q] = 0.f;

    const int lrow = (lane & 15) * 48 + (lane >> 4) * 16;
    const int colb = ((lane & 3) * 2) * 2;
    const int nit = ncc * 9;

    for (int i = 0; i < nit; i++) {
        const int ccl = i / 9, dt = i - ccl * 9;
        char* buf = sm + (i & 1) * 9216;
        CP_WAIT0();
        __syncthreads();
        if (i + 1 < nit) { prefW(cc0 * 9 + i + 1, sm + ((i + 1) & 1) * 9216); CP_COMMIT(); }
        if (dt == 0 && ccl + 1 < ncc) loadX(cc0 + ccl + 1);
        if (dt == 7 && ccl + 1 < ncc) stsX((ccl + 1) & 1);

        const char* Xh = sm + K2_WSZ + (ccl & 1) * K2_XB;
        const char* Xl = Xh + 12672;
        unsigned bh[4][2], bl[4][2];
#pragma unroll
        for (int nb = 0; nb < 4; nb++) {
            int tt = w * 32 + nb * 8 + (lane >> 2) + dt;
            const char* ph = Xh + tt * 48 + colb;
            const char* pl = Xl + tt * 48 + colb;
            bh[nb][0] = *(const unsigned*)ph; bh[nb][1] = *(const unsigned*)(ph + 16);
            bl[nb][0] = *(const unsigned*)pl; bl[nb][1] = *(const unsigned*)(pl + 16);
        }
#pragma unroll
        for (int mi = 0; mi < 6; mi++) {
            unsigned Ah[4], Al[4];
            ldsm4(Ah, buf + mi * 768 + lrow);
            ldsm4(Al, buf + 4608 + mi * 768 + lrow);
#pragma unroll
            for (int nb = 0; nb < 4; nb++) {
                mma_bf16(C[mi][nb], Ah, bh[nb][0], bh[nb][1]);
                mma_bf16(C[mi][nb], Ah, bl[nb][0], bl[nb][1]);
                mma_bf16(C[mi][nb], Al, bh[nb][0], bh[nb][1]);
            }
        }
    }

    float* dst = zz ? g_f2b : g_f2;
#pragma unroll
    for (int mi = 0; mi < 6; mi++) {
#pragma unroll
        for (int nb = 0; nb < 4; nb++) {
            int ch0 = mi * 16 + (lane >> 2);
            int tt = t0 + w * 32 + nb * 8 + (lane & 3) * 2;
            float b0 = zz ? 0.f : g_B2[ch0];
            float b1 = zz ? 0.f : g_B2[ch0 + 8];
            float2 v0 = make_float2(C[mi][nb][0] + b0, C[mi][nb][1] + b0);
            float2 v1 = make_float2(C[mi][nb][2] + b1, C[mi][nb][3] + b1);
            *(float2*)&dst[((size_t)n * 96 + ch0) * 2048 + tt] = v0;
            *(float2*)&dst[((size_t)n * 96 + ch0 + 8) * 2048 + tt] = v1;
        }
    }
}

// ---------------- stages 3+4 fused (register-blocked) ----------------
__global__ void __launch_bounds__(256) k34(float* __restrict__ out) {
    extern __shared__ float smf[];
    float* F2s = smf;                    // [96][136]
    float* F3s = F2s + 96 * 136;         // [16][132]
    float* W3s = F3s + 16 * 132;         // 7680
    float* W4s = W3s + 7680;             // 3072
    const int n = blockIdx.y;
    const int t0 = blockIdx.x * 128;
    const int tid = threadIdx.x;

    for (int idx = tid; idx < 96 * 136; idx += 256) {
        int c = idx / 136, q = idx - c * 136;
        int t = t0 - 3 + q;
        float v = 0.f;
        if (t >= 0 && t < 2048) {
            size_t o = ((size_t)n * 96 + c) * 2048 + t;
            v = g_f2[o] + g_f2b[o];
        }
        F2s[idx] = v;
    }
    for (int idx = tid; idx < 7680; idx += 256) W3s[idx] = g_W3[idx];
    for (int idx = tid; idx < 3072; idx += 256) W4s[idx] = g_W4t[idx];
    __syncthreads();

    for (int idx = tid; idx < 16 * 33; idx += 256) {
        int o = idx / 33, q = idx - 33 * (idx / 33);
        int tp0 = 4 * q;
        float bb = g_B3[o];
        float acc[4] = {bb, bb, bb, bb};
        const float* wr = W3s + o * 480;
        for (int c = 0; c < 96; c++) {
            float4 A = *(const float4*)(F2s + c * 136 + tp0);
            float4 Bv = *(const float4*)(F2s + c * 136 + tp0 + 4);
            float f[8] = {A.x, A.y, A.z, A.w, Bv.x, Bv.y, Bv.z, Bv.w};
#pragma unroll
            for (int dk = 0; dk < 5; dk++) {
                float wv = wr[c * 5 + dk];
#pragma unroll
                for (int j = 0; j < 4; j++) acc[j] = fmaf(wv, f[j + dk], acc[j]);
            }
        }
#pragma unroll
        for (int j = 0; j < 4; j++) {
            int tp = tp0 + j;
            int t3 = t0 - 1 + tp;
            float v = 0.f;
            if (tp < 130 && t3 >= 0 && t3 < 2048)
                v = acc[j] > 0.f ? acc[j] : 0.01f * acc[j];
            F3s[o * 132 + tp] = v;
        }
    }
    __syncthreads();

#pragma unroll
    for (int u = 0; u < 8; u++) {
        int idx = tid + u * 256;
        int tl = idx & 127, o0 = (idx >> 7) * 4;
        float acc[4];
#pragma unroll
        for (int i = 0; i < 4; i++) acc[i] = g_B4[o0 + i];
        for (int c = 0; c < 16; c++) {
            float fv[3] = {F3s[c * 132 + tl], F3s[c * 132 + tl + 1], F3s[c * 132 + tl + 2]};
#pragma unroll
            for (int dk = 0; dk < 3; dk++) {
                float4 wv = *(const float4*)(W4s + (c * 3 + dk) * 64 + o0);
                acc[0] = fmaf(wv.x, fv[dk], acc[0]);
                acc[1] = fmaf(wv.y, fv[dk], acc[1]);
                acc[2] = fmaf(wv.z, fv[dk], acc[2]);
                acc[3] = fmaf(wv.w, fv[dk], acc[3]);
            }
        }
        float4 r;
        r.x = acc[0] > 0.f ? acc[0] : 0.01f * acc[0];
        r.y = acc[1] > 0.f ? acc[1] : 0.01f * acc[1];
        r.z = acc[2] > 0.f ? acc[2] : 0.01f * acc[2];
        r.w = acc[3] > 0.f ? acc[3] : 0.01f * acc[3];
        *(float4*)&out[((size_t)n * 2048 + t0 + tl) * 64 + o0] = r;
    }
}

// ---------------- launch ----------------
extern "C" void kernel_launch(void* const* d_in, const int* in_sizes, int n_in,
                              void* d_out, int out_size) {
    (void)in_sizes; (void)n_in; (void)out_size;
    const float* poses = (const float*)d_in[0];
    const float* A1 = (const float*)d_in[1];
    const float* A2 = (const float*)d_in[2];
    const float* w1 = (const float*)d_in[3];
    const float* b1 = (const float*)d_in[4];
    const float* g1 = (const float*)d_in[5];
    const float* be1 = (const float*)d_in[6];
    const float* m1 = (const float*)d_in[7];
    const float* v1 = (const float*)d_in[8];
    const float* w2 = (const float*)d_in[9];
    const float* b2 = (const float*)d_in[10];
    const float* g2 = (const float*)d_in[11];
    const float* be2 = (const float*)d_in[12];
    const float* m2 = (const float*)d_in[13];
    const float* v2 = (const float*)d_in[14];
    const float* w3 = (const float*)d_in[15];
    const float* b3 = (const float*)d_in[16];
    const float* g3 = (const float*)d_in[17];
    const float* be3 = (const float*)d_in[18];
    const float* m3 = (const float*)d_in[19];
    const float* v3 = (const float*)d_in[20];
    const float* w4 = (const float*)d_in[21];
    const float* b4 = (const float*)d_in[22];
    const float* g4 = (const float*)d_in[23];
    const float* be4 = (const float*)d_in[24];
    const float* m4 = (const float*)d_in[25];
    const float* v4 = (const float*)d_in[26];
    float* out = (float*)d_out;

    size_t sm1 = 91392;
    size_t sm2 = 69120;
    size_t sm34 = (96 * 136 + 16 * 132 + 7680 + 3072) * sizeof(float);  // 103680
    cudaFuncSetAttribute(k1, cudaFuncAttributeMaxDynamicSharedMemorySize, (int)sm1);
    cudaFuncSetAttribute(k2, cudaFuncAttributeMaxDynamicSharedMemorySize, (int)sm2);
    cudaFuncSetAttribute(k34, cudaFuncAttributeMaxDynamicSharedMemorySize, (int)sm34);

    prepAll<<<656, 256>>>(poses,
                          A1, w1, b1, g1, be1, m1, v1,
                          A2, w2, b2, g2, be2, m2, v2,
                          w3, b3, g3, be3, m3, v3,
                          w4, b4, g4, be4, m4, v4);
    k1<<<dim3(8, 16, 4), 256, sm1>>>();
    k2<<<dim3(8, 16, 2), 256, sm2>>>();
    k34<<<dim3(16, 16), 256, sm34>>>(out);
}

// round 7
// speedup vs baseline: 2.6646x; 1.0322x over previous
#include <cuda_runtime.h>
#include <cuda_bf16.h>

#define EPSV 1e-5f

// ---------------- device scratch ----------------
__device__ __align__(16) unsigned short g_W1h[36 * 17 * 16 * 24];
__device__ __align__(16) unsigned short g_W1l[36 * 17 * 16 * 24];
__device__ __align__(16) unsigned short g_W2h[153 * 6 * 16 * 24];
__device__ __align__(16) unsigned short g_W2l[153 * 6 * 16 * 24];
__device__ float g_B1[272];
__device__ float g_B2[96];
__device__ float g_W3[16 * 480];
__device__ float g_B3[16];
__device__ float g_W4t[48 * 64];     // transposed: [k=c*3+dk][o]
__device__ float g_B4[64];
__device__ __align__(16) unsigned short g_Ph[16 * 2048 * 64];
__device__ __align__(16) unsigned short g_Pl[16 * 2048 * 64];
__device__ __align__(16) unsigned short g_f1h[16 * 272 * 2048];
__device__ __align__(16) unsigned short g_f1l[16 * 272 * 2048];
__device__ float g_f2[16 * 96 * 2048];    // K-split partial 0 (with bias)
__device__ float g_f2b[16 * 96 * 2048];   // K-split partial 1

__constant__ int c_part_of[17] = {1,2,3,1,1,4,4,5,5,2,2,3,3,0,0,0,0};
__constant__ int c_idx_of[17]  = {0,0,0,1,2,0,1,0,1,1,2,1,2,0,1,2,3};
__constant__ int c_len_of[6]   = {4,3,3,3,2,2};

// ---------------- helpers ----------------
__device__ __forceinline__ void split_bf16(float x, unsigned short& h, unsigned short& l) {
    __nv_bfloat16 bh = __float2bfloat16(x);
    float r = x - __bfloat162float(bh);
    __nv_bfloat16 bl = __float2bfloat16(r);
    h = __bfloat16_as_ushort(bh);
    l = __bfloat16_as_ushort(bl);
}

__device__ __forceinline__ void ldsm4(unsigned r[4], const void* p) {
    unsigned a = (unsigned)__cvta_generic_to_shared(p);
    asm volatile("ldmatrix.sync.aligned.m8n8.x4.shared.b16 {%0,%1,%2,%3},[%4];"
                 : "=r"(r[0]), "=r"(r[1]), "=r"(r[2]), "=r"(r[3]) : "r"(a));
}

__device__ __forceinline__ void mma_bf16(float* c, const unsigned* a, unsigned b0, unsigned b1) {
    asm volatile("mma.sync.aligned.m16n8k16.row.col.f32.bf16.bf16.f32 "
                 "{%0,%1,%2,%3},{%4,%5,%6,%7},{%8,%9},{%0,%1,%2,%3};"
                 : "+f"(c[0]), "+f"(c[1]), "+f"(c[2]), "+f"(c[3])
                 : "r"(a[0]), "r"(a[1]), "r"(a[2]), "r"(a[3]), "r"(b0), "r"(b1));
}

__device__ __forceinline__ void cpa16(void* dst, const void* src) {
    unsigned d = (unsigned)__cvta_generic_to_shared(dst);
    asm volatile("cp.async.cg.shared.global [%0], [%1], 16;" :: "r"(d), "l"(src));
}
__device__ __forceinline__ void cpa16z(void* dst, const void* src, bool valid) {
    unsigned d = (unsigned)__cvta_generic_to_shared(dst);
    int sz = valid ? 16 : 0;
    asm volatile("cp.async.cg.shared.global [%0], [%1], 16, %2;" :: "r"(d), "l"(src), "r"(sz));
}
#define CP_COMMIT() asm volatile("cp.async.commit_group;")
#define CP_WAIT0()  asm volatile("cp.async.wait_group 0;")

// ---------------- single fused prep kernel (656 blocks x 256 thr) ----------------
__global__ void prepAll(const float* __restrict__ poses,
                        const float* __restrict__ A1, const float* __restrict__ w1,
                        const float* __restrict__ b1, const float* __restrict__ g1,
                        const float* __restrict__ be1, const float* __restrict__ m1,
                        const float* __restrict__ v1,
                        const float* __restrict__ A2, const float* __restrict__ w2,
                        const float* __restrict__ b2, const float* __restrict__ g2,
                        const float* __restrict__ be2, const float* __restrict__ m2,
                        const float* __restrict__ v2,
                        const float* __restrict__ w3, const float* __restrict__ b3,
                        const float* __restrict__ g3, const float* __restrict__ be3,
                        const float* __restrict__ m3, const float* __restrict__ v3,
                        const float* __restrict__ w4, const float* __restrict__ b4,
                        const float* __restrict__ g4, const float* __restrict__ be4,
                        const float* __restrict__ m4, const float* __restrict__ v4) {
    const int bid = blockIdx.x;
    if (bid < 256) {
        const int n = bid >> 4, tb = (bid & 15) * 128;
        for (int idx = threadIdx.x; idx < 128 * 64; idx += 256) {
            int tl = idx >> 6, col = idx & 63;
            int t = tb + tl;
            float v = (col < 51) ? poses[((size_t)n * 2048 + t) * 51 + col] : 0.f;
            unsigned short h, l;
            split_bf16(v, h, l);
            size_t o = ((size_t)n * 2048 + t) * 64 + col;
            g_Ph[o] = h; g_Pl[o] = l;
        }
    } else if (bid < 528) {
        int cw = bid - 256;
        int c = cw / 17, w = cw % 17;
        int mt = cw >> 4, row = cw & 15;
        float s = g1[cw] * rsqrtf(v1[cw] + EPSV);
        for (int e = threadIdx.x; e < 36 * 24; e += 256) {
            int it = e / 24, col = e % 24;
            int dt = it >> 2, rc = it & 3;
            int r = rc * 16 + col;
            float val = 0.f;
            if (col < 16 && r < 51) {
                int u = r / 3, ci = r % 3;
                for (int k = 0; k < 5; k++)
                    for (int dv = 0; dv < 5; dv++) {
                        int v = u - dv + 2;
                        if (v >= 0 && v < 17)
                            val += A1[(k * 17 + v) * 17 + w] *
                                   w1[(((k * 16 + c) * 3 + ci) * 9 + dt) * 5 + dv];
                    }
                val *= s;
            }
            unsigned short h, l;
            split_bf16(val, h, l);
            int idx = ((it * 17 + mt) * 16 + row) * 24 + col;
            g_W1h[idx] = h; g_W1l[idx] = l;
        }
        if (threadIdx.x == 0) {
            float bias = 0.f;
            for (int k = 0; k < 5; k++) {
                float sa = 0.f;
                for (int v = 0; v < 17; v++) sa += A1[(k * 17 + v) * 17 + w];
                bias += b1[k * 16 + c] * sa;
            }
            g_B1[cw] = (bias - m1[cw]) * s + be1[cw];
        }
    } else if (bid < 624) {
        int cw = bid - 528;
        int c = cw / 6, w = cw % 6;
        int mt = cw >> 4, row = cw & 15;
        float s = g2[cw] * rsqrtf(v2[cw] + EPSV);
        for (int e = threadIdx.x; e < 153 * 24; e += 256) {
            int it = e / 24, col = e % 24;
            int cc = it / 9, dt = it % 9;
            int ch = cc * 16 + col;
            float val = 0.f;
            if (col < 16) {
                int f = ch / 17, jt = ch % 17;
                int p = c_part_of[jt], j = c_idx_of[jt], ln = c_len_of[p];
                int ci = f * ln + j;
                for (int k = 0; k < 5; k++)
                    for (int v = 0; v < 6; v++) {
                        int dp = p - v + 1;
                        if (dp >= 0 && dp < 3)
                            val += A2[(k * 6 + v) * 6 + w] *
                                   w2[(((k * 16 + c) * 64 + ci) * 9 + dt) * 3 + dp];
                    }
                val *= s;
            }
            unsigned short h, l;
            split_bf16(val, h, l);
            int idx = ((it * 6 + mt) * 16 + row) * 24 + col;
            g_W2h[idx] = h; g_W2l[idx] = l;
        }
        if (threadIdx.x == 0) {
            float bias = 0.f;
            for (int k = 0; k < 5; k++) {
                float sa = 0.f;
                for (int v = 0; v < 6; v++) sa += A2[(k * 6 + v) * 6 + w];
                bias += b2[k * 16 + c] * sa;
            }
            g_B2[cw] = (bias - m2[cw]) * s + be2[cw];
        }
    } else {
        int base = (bid - 624) * 256 + threadIdx.x;
        if (base < 7680) {
            int o = base / 480;
            g_W3[base] = w3[base] * (g3[o] * rsqrtf(v3[o] + EPSV));
        }
        if (base < 3072) {
            int o = base / 48, k = base % 48;
            g_W4t[k * 64 + o] = w4[base] * (g4[o] * rsqrtf(v4[o] + EPSV));
        }
        if (base < 16) {
            float s = g3[base] * rsqrtf(v3[base] + EPSV);
            g_B3[base] = (b3[base] - m3[base]) * s + be3[base];
        }
        if (base >= 32 && base < 96) {
            int o = base - 32;
            float s = g4[o] * rsqrtf(v4[o] + EPSV);
            g_B4[o] = (b4[o] - m4[o]) * s + be4[o];
        }
    }
}

// ---------------- stage 1 tensor GEMM ----------------
#define K1_XOFF 15360
#define K1_XSZ  38016
__global__ void __launch_bounds__(256, 2) k1() {
    extern __shared__ char sm[];
    const int n = blockIdx.y, t0 = blockIdx.x * 256;
    const int z = blockIdx.z;
    const int mt0 = (z == 0) ? 0 : 1 + z * 4;
    const int mcount = (z == 0) ? 5 : 4;
    const int tid = threadIdx.x, lane = tid & 31, w = tid >> 5;

    char* Xh = sm + K1_XOFF;
    char* Xl = sm + K1_XOFF + K1_XSZ;

    auto prefW = [&](int it, char* buf) {
        const char* srcH = (const char*)(g_W1h + (size_t)(it * 17 + mt0) * 384);
        const char* srcL = (const char*)(g_W1l + (size_t)(it * 17 + mt0) * 384);
        int cnt = mcount * 48;
        for (int i = tid; i < cnt; i += 256) {
            cpa16(buf + i * 16, srcH + i * 16);
            cpa16(buf + 3840 + i * 16, srcL + i * 16);
        }
    };

    for (int i = tid; i < 264 * 8; i += 256) {
        int row = i >> 3, q = i & 7;
        int t = t0 - 4 + row;
        bool valid = (t >= 0 && t < 2048);
        size_t so = ((size_t)n * 2048 + (valid ? t : 0)) * 64 + q * 8;
        cpa16z(Xh + row * 144 + q * 16, g_Ph + so, valid);
        cpa16z(Xl + row * 144 + q * 16, g_Pl + so, valid);
    }
    prefW(0, sm);
    CP_COMMIT();

    float C[5][4][4];
#pragma unroll
    for (int i = 0; i < 5; i++)
#pragma unroll
        for (int j = 0; j < 4; j++)
#pragma unroll
            for (int q = 0; q < 4; q++) C[i][j][q] = 0.f;

    const int lrow = (lane & 15) * 48 + (lane >> 4) * 16;

    for (int it = 0; it < 36; it++) {
        char* buf = sm + (it & 1) * 7680;
        CP_WAIT0();
        __syncthreads();
        if (it + 1 < 36) { prefW(it + 1, sm + ((it + 1) & 1) * 7680); CP_COMMIT(); }

        const int dt = it >> 2, rc = it & 3;
        const int colb = (rc * 16 + (lane & 3) * 2) * 2;
        unsigned bh[4][2], bl[4][2];
#pragma unroll
        for (int nb = 0; nb < 4; nb++) {
            int tt = w * 32 + nb * 8 + (lane >> 2) + dt;
            const char* ph = Xh + tt * 144 + colb;
            const char* pl = Xl + tt * 144 + colb;
            bh[nb][0] = *(const unsigned*)ph; bh[nb][1] = *(const unsigned*)(ph + 16);
            bl[nb][0] = *(const unsigned*)pl; bl[nb][1] = *(const unsigned*)(pl + 16);
        }
        for (int mi = 0; mi < mcount; mi++) {
            unsigned Ah[4], Al[4];
            ldsm4(Ah, buf + mi * 768 + lrow);
            ldsm4(Al, buf + 3840 + mi * 768 + lrow);
#pragma unroll
            for (int nb = 0; nb < 4; nb++) {
                mma_bf16(C[mi][nb], Ah, bh[nb][0], bh[nb][1]);
                mma_bf16(C[mi][nb], Ah, bl[nb][0], bl[nb][1]);
                mma_bf16(C[mi][nb], Al, bh[nb][0], bh[nb][1]);
            }
        }
    }

    for (int mi = 0; mi < mcount; mi++) {
#pragma unroll
        for (int nb = 0; nb < 4; nb++) {
            int ch0 = (mt0 + mi) * 16 + (lane >> 2);
            int tt = t0 + w * 32 + nb * 8 + (lane & 3) * 2;
            float b0 = g_B1[ch0], b1 = g_B1[ch0 + 8];
            unsigned short h0, l0, h1, l1;
            size_t o0 = ((size_t)n * 272 + ch0) * 2048 + tt;
            split_bf16(C[mi][nb][0] + b0, h0, l0);
            split_bf16(C[mi][nb][1] + b0, h1, l1);
            *(unsigned*)&g_f1h[o0] = (unsigned)h0 | ((unsigned)h1 << 16);
            *(unsigned*)&g_f1l[o0] = (unsigned)l0 | ((unsigned)l1 << 16);
            size_t o1 = ((size_t)n * 272 + ch0 + 8) * 2048 + tt;
            split_bf16(C[mi][nb][2] + b1, h0, l0);
            split_bf16(C[mi][nb][3] + b1, h1, l1);
            *(unsigned*)&g_f1h[o1] = (unsigned)h0 | ((unsigned)h1 << 16);
            *(unsigned*)&g_f1l[o1] = (unsigned)l0 | ((unsigned)l1 << 16);
        }
    }
}

// ---------------- stage 2 tensor GEMM (K-split over z) ----------------
#define K2_WSZ 18432
#define K2_XB  25344
__global__ void __launch_bounds__(256, 2) k2() {
    extern __shared__ char sm[];
    const int n = blockIdx.y, t0 = blockIdx.x * 256;
    const int zz = blockIdx.z;
    const int cc0 = zz ? 9 : 0;
    const int ncc = zz ? 8 : 9;
    const int tid = threadIdx.x, lane = tid & 31, w = tid >> 5;
    const int g = tid & 15, jj = tid >> 4;

    unsigned sh[9], sl[9];

    auto prefW = [&](int it, char* buf) {
        const char* srcH = (const char*)(g_W2h + (size_t)it * 2304);
        const char* srcL = (const char*)(g_W2l + (size_t)it * 2304);
        for (int i = tid; i < 288; i += 256) {
            cpa16(buf + i * 16, srcH + i * 16);
            cpa16(buf + 4608 + i * 16, srcL + i * 16);
        }
    };
    auto loadX = [&](int cc) {
        size_t base = ((size_t)n * 272 + cc * 16 + g) * 2048;
#pragma unroll
        for (int i = 0; i < 9; i++) {
            int p = jj + 16 * i;
            sh[i] = 0; sl[i] = 0;
            if (p < 132) {
                int t = t0 - 4 + 2 * p;
                if (t >= 0 && t < 2048) {
                    sh[i] = *(const unsigned*)(g_f1h + base + t);
                    sl[i] = *(const unsigned*)(g_f1l + base + t);
                }
            }
        }
    };
    auto stsX = [&](int buf) {
        unsigned short* Xh = (unsigned short*)(sm + K2_WSZ + buf * K2_XB);
        unsigned short* Xl = (unsigned short*)(sm + K2_WSZ + buf * K2_XB + 12672);
#pragma unroll
        for (int i = 0; i < 9; i++) {
            int p = jj + 16 * i;
            if (p < 132) {
                Xh[(2 * p) * 24 + g] = (unsigned short)(sh[i] & 0xffff);
                Xh[(2 * p + 1) * 24 + g] = (unsigned short)(sh[i] >> 16);
                Xl[(2 * p) * 24 + g] = (unsigned short)(sl[i] & 0xffff);
                Xl[(2 * p + 1) * 24 + g] = (unsigned short)(sl[i] >> 16);
            }
        }
    };

    loadX(cc0);
    stsX(0);
    prefW(cc0 * 9, sm);
    CP_COMMIT();

    float C[6][4][4];
#pragma unroll
    for (int i = 0; i < 6; i++)
#pragma unroll
        for (int j = 0; j < 4; j++)
#pragma unroll
            for (int q = 0; q < 4; q++) C[i][j][q] = 0.f;

    const int lrow = (lane & 15) * 48 + (lane >> 4) * 16;
    const int colb = ((lane & 3) * 2) * 2;
    const int nit = ncc * 9;

    for (int i = 0; i < nit; i++) {
        const int ccl = i / 9, dt = i - ccl * 9;
        char* buf = sm + (i & 1) * 9216;
        CP_WAIT0();
        __syncthreads();
        if (i + 1 < nit) { prefW(cc0 * 9 + i + 1, sm + ((i + 1) & 1) * 9216); CP_COMMIT(); }
        if (dt == 0 && ccl + 1 < ncc) loadX(cc0 + ccl + 1);
        if (dt == 7 && ccl + 1 < ncc) stsX((ccl + 1) & 1);

        const char* Xh = sm + K2_WSZ + (ccl & 1) * K2_XB;
        const char* Xl = Xh + 12672;
        unsigned bh[4][2], bl[4][2];
#pragma unroll
        for (int nb = 0; nb < 4; nb++) {
            int tt = w * 32 + nb * 8 + (lane >> 2) + dt;
            const char* ph = Xh + tt * 48 + colb;
            const char* pl = Xl + tt * 48 + colb;
            bh[nb][0] = *(const unsigned*)ph; bh[nb][1] = *(const unsigned*)(ph + 16);
            bl[nb][0] = *(const unsigned*)pl; bl[nb][1] = *(const unsigned*)(pl + 16);
        }
#pragma unroll
        for (int mi = 0; mi < 6; mi++) {
            unsigned Ah[4], Al[4];
            ldsm4(Ah, buf + mi * 768 + lrow);
            ldsm4(Al, buf + 4608 + mi * 768 + lrow);
#pragma unroll
            for (int nb = 0; nb < 4; nb++) {
                mma_bf16(C[mi][nb], Ah, bh[nb][0], bh[nb][1]);
                mma_bf16(C[mi][nb], Ah, bl[nb][0], bl[nb][1]);
                mma_bf16(C[mi][nb], Al, bh[nb][0], bh[nb][1]);
            }
        }
    }

    float* dst = zz ? g_f2b : g_f2;
#pragma unroll
    for (int mi = 0; mi < 6; mi++) {
#pragma unroll
        for (int nb = 0; nb < 4; nb++) {
            int ch0 = mi * 16 + (lane >> 2);
            int tt = t0 + w * 32 + nb * 8 + (lane & 3) * 2;
            float b0 = zz ? 0.f : g_B2[ch0];
            float b1 = zz ? 0.f : g_B2[ch0 + 8];
            float2 v0 = make_float2(C[mi][nb][0] + b0, C[mi][nb][1] + b0);
            float2 v1 = make_float2(C[mi][nb][2] + b1, C[mi][nb][3] + b1);
            *(float2*)&dst[((size_t)n * 96 + ch0) * 2048 + tt] = v0;
            *(float2*)&dst[((size_t)n * 96 + ch0 + 8) * 2048 + tt] = v1;
        }
    }
}

// ---------------- stages 3+4 fused (bank-conflict-free, 2 CTAs/SM) ----------------
// smem: F2s [96][144] | F3s [16][132] | W3s [16][481]  = 94528 B
__global__ void __launch_bounds__(256, 2) k34(float* __restrict__ out) {
    extern __shared__ float smf[];
    float* F2s = smf;
    float* F3s = smf + 96 * 144;
    float* W3s = F3s + 16 * 132;
    const int n = blockIdx.y;
    const int t0 = blockIdx.x * 128;
    const int tid = threadIdx.x;

    for (int idx = tid; idx < 96 * 144; idx += 256) {
        int c = idx / 144, q = idx - c * 144;
        int t = t0 - 3 + q;
        float v = 0.f;
        if (q < 136 && t >= 0 && t < 2048) {
            size_t o = ((size_t)n * 96 + c) * 2048 + t;
            v = g_f2[o] + g_f2b[o];
        }
        F2s[idx] = v;
    }
    for (int idx = tid; idx < 16 * 480; idx += 256) {
        int o = idx / 480, k = idx - o * 480;
        W3s[o * 481 + k] = g_W3[idx];
    }
    __syncthreads();

    // f3: idx = q*16 + o (q 0..16, o 0..15) -> activations broadcast across lanes,
    //     weights stride 481 (== 1 mod 32) -> conflict-free banks
    for (int idx = tid; idx < 272; idx += 256) {
        int q = idx >> 4, o = idx & 15;
        int tp0 = q * 8;
        float bb = __ldg(&g_B3[o]);
        float acc[8];
#pragma unroll
        for (int j = 0; j < 8; j++) acc[j] = bb;
        const float* wr = W3s + o * 481;
        for (int c = 0; c < 96; c++) {
            const float* fp = F2s + c * 144 + tp0;
            float4 A = *(const float4*)fp;
            float4 Bv = *(const float4*)(fp + 4);
            float4 Cv = *(const float4*)(fp + 8);
            float f[12] = {A.x, A.y, A.z, A.w, Bv.x, Bv.y, Bv.z, Bv.w,
                           Cv.x, Cv.y, Cv.z, Cv.w};
            const float* wc = wr + c * 5;
#pragma unroll
            for (int dk = 0; dk < 5; dk++) {
                float wv = wc[dk];
#pragma unroll
                for (int j = 0; j < 8; j++) acc[j] = fmaf(wv, f[j + dk], acc[j]);
            }
        }
#pragma unroll
        for (int j = 0; j < 8; j++) {
            int tp = tp0 + j;
            int t3 = t0 - 1 + tp;
            float v = 0.f;
            if (tp < 130 && t3 >= 0 && t3 < 2048)
                v = acc[j] > 0.f ? acc[j] : 0.01f * acc[j];
            if (tp < 132) F3s[o * 132 + tp] = v;
        }
    }
    __syncthreads();

    // f4: weights via uniform __ldg float4 (L1 broadcast), coalesced STG.128
#pragma unroll
    for (int u = 0; u < 8; u++) {
        int idx = tid + u * 256;
        int tl = idx & 127, o0 = (idx >> 7) * 4;
        float acc[4];
#pragma unroll
        for (int i = 0; i < 4; i++) acc[i] = __ldg(&g_B4[o0 + i]);
        for (int c = 0; c < 16; c++) {
            float fv[3] = {F3s[c * 132 + tl], F3s[c * 132 + tl + 1], F3s[c * 132 + tl + 2]};
#pragma unroll
            for (int dk = 0; dk < 3; dk++) {
                float4 wv = __ldg((const float4*)(g_W4t + (c * 3 + dk) * 64 + o0));
                acc[0] = fmaf(wv.x, fv[dk], acc[0]);
                acc[1] = fmaf(wv.y, fv[dk], acc[1]);
                acc[2] = fmaf(wv.z, fv[dk], acc[2]);
                acc[3] = fmaf(wv.w, fv[dk], acc[3]);
            }
        }
        float4 r;
        r.x = acc[0] > 0.f ? acc[0] : 0.01f * acc[0];
        r.y = acc[1] > 0.f ? acc[1] : 0.01f * acc[1];
        r.z = acc[2] > 0.f ? acc[2] : 0.01f * acc[2];
        r.w = acc[3] > 0.f ? acc[3] : 0.01f * acc[3];
        *(float4*)&out[((size_t)n * 2048 + t0 + tl) * 64 + o0] = r;
    }
}

// ---------------- launch ----------------
extern "C" void kernel_launch(void* const* d_in, const int* in_sizes, int n_in,
                              void* d_out, int out_size) {
    (void)in_sizes; (void)n_in; (void)out_size;
    const float* poses = (const float*)d_in[0];
    const float* A1 = (const float*)d_in[1];
    const float* A2 = (const float*)d_in[2];
    const float* w1 = (const float*)d_in[3];
    const float* b1 = (const float*)d_in[4];
    const float* g1 = (const float*)d_in[5];
    const float* be1 = (const float*)d_in[6];
    const float* m1 = (const float*)d_in[7];
    const float* v1 = (const float*)d_in[8];
    const float* w2 = (const float*)d_in[9];
    const float* b2 = (const float*)d_in[10];
    const float* g2 = (const float*)d_in[11];
    const float* be2 = (const float*)d_in[12];
    const float* m2 = (const float*)d_in[13];
    const float* v2 = (const float*)d_in[14];
    const float* w3 = (const float*)d_in[15];
    const float* b3 = (const float*)d_in[16];
    const float* g3 = (const float*)d_in[17];
    const float* be3 = (const float*)d_in[18];
    const float* m3 = (const float*)d_in[19];
    const float* v3 = (const float*)d_in[20];
    const float* w4 = (const float*)d_in[21];
    const float* b4 = (const float*)d_in[22];
    const float* g4 = (const float*)d_in[23];
    const float* be4 = (const float*)d_in[24];
    const float* m4 = (const float*)d_in[25];
    const float* v4 = (const float*)d_in[26];
    float* out = (float*)d_out;

    size_t sm1 = 91392;
    size_t sm2 = 69120;
    size_t sm34 = (96 * 144 + 16 * 132 + 16 * 481) * sizeof(float);  // 94528
    cudaFuncSetAttribute(k1, cudaFuncAttributeMaxDynamicSharedMemorySize, (int)sm1);
    cudaFuncSetAttribute(k2, cudaFuncAttributeMaxDynamicSharedMemorySize, (int)sm2);
    cudaFuncSetAttribute(k34, cudaFuncAttributeMaxDynamicSharedMemorySize, (int)sm34);

    prepAll<<<656, 256>>>(poses,
                          A1, w1, b1, g1, be1, m1, v1,
                          A2, w2, b2, g2, be2, m2, v2,
                          w3, b3, g3, be3, m3, v3,
                          w4, b4, g4, be4, m4, v4);
    k1<<<dim3(8, 16, 4), 256, sm1>>>();
    k2<<<dim3(8, 16, 2), 256, sm2>>>();
    k34<<<dim3(16, 16), 256, sm34>>>(out);
}